// round 1
// baseline (speedup 1.0000x reference)
#include <cuda_runtime.h>
#include <cuda_bf16.h>

#define N_NODES 100000
#define F_IN    64
#define HID     128

// Scratch (device globals — no runtime allocation allowed)
__device__ float g_agg1[N_NODES * F_IN];   // 25.6 MB
__device__ float g_h   [N_NODES * HID];    // 51.2 MB
__device__ float g_agg2[N_NODES * HID];    // 51.2 MB
__device__ float g_cnt [N_NODES];          // in-degree -> reciprocal

// ---------------------------------------------------------------------------
// Vector fp32 reduction to global (sm_90+): 4 floats per instruction
// ---------------------------------------------------------------------------
__device__ __forceinline__ void red_add_v4(float* p, float4 v) {
    asm volatile("red.global.add.v4.f32 [%0], {%1, %2, %3, %4};"
                 :: "l"(p), "f"(v.x), "f"(v.y), "f"(v.z), "f"(v.w)
                 : "memory");
}

// ---------------------------------------------------------------------------
// Zeroing kernels (accumulators must start at 0; d_out is poisoned by harness)
// ---------------------------------------------------------------------------
__global__ void zero_agg1_cnt() {
    int i = blockIdx.x * blockDim.x + threadIdx.x;
    const float4 z = make_float4(0.f, 0.f, 0.f, 0.f);
    if (i < N_NODES * F_IN / 4) reinterpret_cast<float4*>(g_agg1)[i] = z;
    if (i < N_NODES / 4)        reinterpret_cast<float4*>(g_cnt)[i]  = z;
}

__global__ void zero_agg2() {
    int i = blockIdx.x * blockDim.x + threadIdx.x;
    const float4 z = make_float4(0.f, 0.f, 0.f, 0.f);
    if (i < N_NODES * HID / 4) reinterpret_cast<float4*>(g_agg2)[i] = z;
}

// ---------------------------------------------------------------------------
// Layer-1 scatter: 16 threads per edge (64 floats = 16 float4), plus degree
// ---------------------------------------------------------------------------
__global__ void scatter1(const float4* __restrict__ x4,
                         const int* __restrict__ ei, int E) {
    int idx = blockIdx.x * blockDim.x + threadIdx.x;
    int e = idx >> 4;
    if (e >= E) return;
    int q   = idx & 15;
    int src = __ldg(ei + e);
    int dst = __ldg(ei + E + e);
    float4 v = __ldg(x4 + (size_t)src * 16 + q);
    red_add_v4(&g_agg1[(size_t)dst * F_IN + q * 4], v);
    if (q == 0) atomicAdd(&g_cnt[dst], 1.0f);
}

// ---------------------------------------------------------------------------
// Layer-2 scatter: 32 threads per edge (128 floats = 32 float4)
// ---------------------------------------------------------------------------
__global__ void scatter2(const int* __restrict__ ei, int E) {
    int idx = blockIdx.x * blockDim.x + threadIdx.x;
    int e = idx >> 5;
    if (e >= E) return;
    int q   = idx & 31;
    int src = __ldg(ei + e);
    int dst = __ldg(ei + E + e);
    float4 v = __ldg(reinterpret_cast<const float4*>(g_h) + (size_t)src * 32 + q);
    red_add_v4(&g_agg2[(size_t)dst * HID + q * 4], v);
}

// cnt -> 1/max(cnt,1)  (used by both GEMMs)
__global__ void inv_cnt() {
    int i = blockIdx.x * blockDim.x + threadIdx.x;
    if (i < N_NODES) g_cnt[i] = 1.0f / fmaxf(g_cnt[i], 1.0f);
}

// ---------------------------------------------------------------------------
// Fused SAGE GEMM:
//   out[m, 0:128] = (agg[m]/cnt[m]) @ WL^T + X[m] @ WR^T + bias   (opt. ReLU)
// Virtual input = concat(mean, X)  -> K = 2*KH ; virtual W = [WL | WR].
// BM=64, BN=128, BK=16, 256 threads, 4x8 register tile per thread.
// ---------------------------------------------------------------------------
template <int KH, bool RELU>
__global__ void __launch_bounds__(256)
sage_gemm(const float* __restrict__ A,     // [M, KH] un-normalized aggregate
          const float* __restrict__ X,     // [M, KH] root features
          const float* __restrict__ INVC,  // [M] 1/max(cnt,1)
          const float* __restrict__ WL,    // [128, KH]
          const float* __restrict__ WR,    // [128, KH]
          const float* __restrict__ bias,  // [128]
          float* __restrict__ out,         // [M, 128]
          int M) {
    constexpr int BM = 64, BN = 128, BK = 16, TM = 4, TN = 8;
    constexpr int K  = 2 * KH;

    __shared__ float As[BK][BM + 1];   // +1 pad: conflict-free transposed store
    __shared__ float Bs[BK][BN];

    const int tid     = threadIdx.x;
    const int block_m = blockIdx.x * BM;

    // compute-tile coords
    const int tn = (tid & 15) * TN;
    const int tm = (tid >> 4) * TM;

    // A-loader: thread -> (row, 4 consecutive k). Row fixed for whole kernel.
    const int a_mm = tid >> 2;          // 0..63
    const int a_kq = (tid & 3) * 4;     // 0,4,8,12
    const int a_row = block_m + a_mm;
    const bool a_ok = (a_row < M);
    const float invc = a_ok ? INVC[a_row] : 0.f;

    float acc[TM][TN];
#pragma unroll
    for (int i = 0; i < TM; ++i)
#pragma unroll
        for (int j = 0; j < TN; ++j) acc[i][j] = 0.f;

    for (int k0 = 0; k0 < K; k0 += BK) {
        // ---- stage A tile (coalesced float4, transposed into smem) ----
        float4 av = make_float4(0.f, 0.f, 0.f, 0.f);
        if (a_ok) {
            if (k0 < KH) {
                av = *reinterpret_cast<const float4*>(A + (size_t)a_row * KH + k0 + a_kq);
                av.x *= invc; av.y *= invc; av.z *= invc; av.w *= invc;
            } else {
                av = *reinterpret_cast<const float4*>(X + (size_t)a_row * KH + (k0 - KH) + a_kq);
            }
        }
        As[a_kq + 0][a_mm] = av.x;
        As[a_kq + 1][a_mm] = av.y;
        As[a_kq + 2][a_mm] = av.z;
        As[a_kq + 3][a_mm] = av.w;

        // ---- stage B tile: 2048 floats = 512 float4, 2 per thread ----
#pragma unroll
        for (int it = 0; it < 2; ++it) {
            int l  = tid + it * 256;    // 0..511 (float4 index)
            int nn = l >> 2;            // 0..127
            int kq = (l & 3) * 4;       // 0,4,8,12
            const float* Wsel = (k0 < KH) ? WL : WR;
            int kbase = (k0 < KH) ? k0 : (k0 - KH);
            float4 bv = *reinterpret_cast<const float4*>(Wsel + (size_t)nn * KH + kbase + kq);
            Bs[kq + 0][nn] = bv.x;
            Bs[kq + 1][nn] = bv.y;
            Bs[kq + 2][nn] = bv.z;
            Bs[kq + 3][nn] = bv.w;
        }
        __syncthreads();

        // ---- compute ----
#pragma unroll
        for (int kk = 0; kk < BK; ++kk) {
            float a[TM], b[TN];
#pragma unroll
            for (int i = 0; i < TM; ++i) a[i] = As[kk][tm + i];
#pragma unroll
            for (int j = 0; j < TN; ++j) b[j] = Bs[kk][tn + j];
#pragma unroll
            for (int i = 0; i < TM; ++i)
#pragma unroll
                for (int j = 0; j < TN; ++j) acc[i][j] += a[i] * b[j];
        }
        __syncthreads();
    }

    // ---- epilogue ----
#pragma unroll
    for (int i = 0; i < TM; ++i) {
        int row = block_m + tm + i;
        if (row >= M) continue;
#pragma unroll
        for (int j = 0; j < TN; ++j) {
            float o = acc[i][j] + bias[tn + j];
            if (RELU) o = fmaxf(o, 0.f);
            out[(size_t)row * HID + tn + j] = o;
        }
    }
}

// ---------------------------------------------------------------------------
extern "C" void kernel_launch(void* const* d_in, const int* in_sizes, int n_in,
                              void* d_out, int out_size) {
    const float* x   = (const float*)d_in[0];
    const int*   ei  = (const int*)  d_in[1];
    const float* Wl1 = (const float*)d_in[2];
    const float* bl1 = (const float*)d_in[3];
    const float* Wr1 = (const float*)d_in[4];
    const float* Wl2 = (const float*)d_in[5];
    const float* bl2 = (const float*)d_in[6];
    const float* Wr2 = (const float*)d_in[7];
    float* out = (float*)d_out;

    const int E = in_sizes[1] / 2;
    const int M = N_NODES;

    float *agg1, *h, *agg2, *cnt;
    cudaGetSymbolAddress((void**)&agg1, g_agg1);
    cudaGetSymbolAddress((void**)&h,    g_h);
    cudaGetSymbolAddress((void**)&agg2, g_agg2);
    cudaGetSymbolAddress((void**)&cnt,  g_cnt);

    const int gemm_blocks = (M + 63) / 64;

    zero_agg1_cnt<<<(N_NODES * F_IN / 4 + 255) / 256, 256>>>();
    scatter1<<<((long)E * 16 + 255) / 256, 256>>>(
        reinterpret_cast<const float4*>(x), ei, E);
    inv_cnt<<<(N_NODES + 255) / 256, 256>>>();
    sage_gemm<F_IN, true><<<gemm_blocks, 256>>>(agg1, x, cnt, Wl1, Wr1, bl1, h, M);
    zero_agg2<<<(N_NODES * HID / 4 + 255) / 256, 256>>>();
    scatter2<<<((long)E * 32 + 255) / 256, 256>>>(ei, E);
    sage_gemm<HID, false><<<gemm_blocks, 256>>>(agg2, h, cnt, Wl2, Wr2, bl2, out, M);
}

// round 2
// speedup vs baseline: 1.2815x; 1.2815x over previous
#include <cuda_runtime.h>
#include <cuda_bf16.h>

#define N_NODES 100000
#define F_IN    64
#define HID     128

// Scratch (device globals — no runtime allocation allowed)
__device__ float g_agg1[N_NODES * F_IN];   // 25.6 MB
__device__ float g_h   [N_NODES * HID];    // 51.2 MB
__device__ float g_agg2[N_NODES * HID];    // 51.2 MB
__device__ float g_cnt [N_NODES];          // in-degree -> reciprocal

// ---------------------------------------------------------------------------
__device__ __forceinline__ void red_add_v4(float* p, float4 v) {
    asm volatile("red.global.add.v4.f32 [%0], {%1, %2, %3, %4};"
                 :: "l"(p), "f"(v.x), "f"(v.y), "f"(v.z), "f"(v.w)
                 : "memory");
}

__device__ __forceinline__ unsigned long long pack2(float f) {
    unsigned long long r;
    unsigned int u = __float_as_uint(f);
    asm("mov.b64 %0, {%1, %1};" : "=l"(r) : "r"(u));
    return r;
}

#define FMA2(d, a, b) \
    asm("fma.rn.f32x2 %0, %1, %2, %0;" : "+l"(d) : "l"(a), "l"(b))

// ---------------------------------------------------------------------------
__global__ void zero_agg1_cnt() {
    int i = blockIdx.x * blockDim.x + threadIdx.x;
    const float4 z = make_float4(0.f, 0.f, 0.f, 0.f);
    if (i < N_NODES * F_IN / 4) reinterpret_cast<float4*>(g_agg1)[i] = z;
    if (i < N_NODES / 4)        reinterpret_cast<float4*>(g_cnt)[i]  = z;
}

__global__ void zero_agg2() {
    int i = blockIdx.x * blockDim.x + threadIdx.x;
    const float4 z = make_float4(0.f, 0.f, 0.f, 0.f);
    if (i < N_NODES * HID / 4) reinterpret_cast<float4*>(g_agg2)[i] = z;
}

// ---------------------------------------------------------------------------
// Layer-1 scatter: 16 threads per edge (64 floats = 16 float4), plus degree
// ---------------------------------------------------------------------------
__global__ void scatter1(const float4* __restrict__ x4,
                         const int* __restrict__ ei, int E) {
    int idx = blockIdx.x * blockDim.x + threadIdx.x;
    int e = idx >> 4;
    if (e >= E) return;
    int q   = idx & 15;
    int src = __ldg(ei + e);
    int dst = __ldg(ei + E + e);
    float4 v = __ldg(x4 + (size_t)src * 16 + q);
    red_add_v4(&g_agg1[(size_t)dst * F_IN + q * 4], v);
    if (q == 0) atomicAdd(&g_cnt[dst], 1.0f);
}

__global__ void scatter2(const int* __restrict__ ei, int E) {
    int idx = blockIdx.x * blockDim.x + threadIdx.x;
    int e = idx >> 5;
    if (e >= E) return;
    int q   = idx & 31;
    int src = __ldg(ei + e);
    int dst = __ldg(ei + E + e);
    float4 v = __ldg(reinterpret_cast<const float4*>(g_h) + (size_t)src * 32 + q);
    red_add_v4(&g_agg2[(size_t)dst * HID + q * 4], v);
}

__global__ void inv_cnt() {
    int i = blockIdx.x * blockDim.x + threadIdx.x;
    if (i < N_NODES) g_cnt[i] = 1.0f / fmaxf(g_cnt[i], 1.0f);
}

// ---------------------------------------------------------------------------
// Fused SAGE GEMM, BM=128 BN=128 BK=16, 256 thr, 8x8/thread, f32x2 FMAs.
//   out[m] = (agg[m]*invc[m]) @ WL^T + X[m] @ WR^T + bias   (opt. ReLU)
// Virtual K = 2*KH (first half WL on mean, second half WR on X).
// ---------------------------------------------------------------------------
template <int KH, bool RELU>
__global__ void __launch_bounds__(256)
sage_gemm(const float* __restrict__ A,     // [M, KH] un-normalized aggregate
          const float* __restrict__ X,     // [M, KH] root features
          const float* __restrict__ INVC,  // [M]
          const float* __restrict__ WL,    // [128, KH]
          const float* __restrict__ WR,    // [128, KH]
          const float* __restrict__ bias,  // [128]
          float* __restrict__ out,         // [M, 128]
          int M) {
    constexpr int BM = 128, BN = 128, BK = 16, TM = 8, TN = 8;
    constexpr int K  = 2 * KH;
    constexpr int LDA = BM + 4;   // 132 floats = 528B: 16B-aligned rows
    constexpr int LDB = BN + 4;

    __shared__ float As[BK][LDA];
    __shared__ float Bs[BK][LDB];

    const int tid     = threadIdx.x;
    const int block_m = blockIdx.x * BM;

    const int tn = (tid & 15) * TN;
    const int tm = (tid >> 4) * TM;

    // loader mapping: l = it*256+tid ; row = l>>2 (0..127), kq = (l&3)*4
    const int l_row = tid >> 2;          // 0..63 (it adds 64)
    const int l_kq  = (tid & 3) * 4;

    // per-loader invc (two rows per thread across the 2 iters)
    float invc0 = 0.f, invc1 = 0.f;
    {
        int r0 = block_m + l_row;
        int r1 = block_m + l_row + 64;
        if (r0 < M) invc0 = INVC[r0];
        if (r1 < M) invc1 = INVC[r1];
    }

    unsigned long long acc[TM][TN / 2];
#pragma unroll
    for (int i = 0; i < TM; ++i)
#pragma unroll
        for (int j = 0; j < TN / 2; ++j) acc[i][j] = 0ull;

    for (int k0 = 0; k0 < K; k0 += BK) {
        const bool  first = (k0 < KH);
        const int   kb    = first ? k0 : (k0 - KH);
        const float* Asrc = first ? A : X;
        const float* Wsel = first ? WL : WR;

        // ---- stage A tile: 128 rows x 16 k = 512 float4, 2/thread ----
#pragma unroll
        for (int it = 0; it < 2; ++it) {
            int mm  = l_row + it * 64;
            int row = block_m + mm;
            float4 av = make_float4(0.f, 0.f, 0.f, 0.f);
            if (row < M) {
                av = *reinterpret_cast<const float4*>(Asrc + (size_t)row * KH + kb + l_kq);
                if (first) {
                    float c = it ? invc1 : invc0;
                    av.x *= c; av.y *= c; av.z *= c; av.w *= c;
                }
            }
            As[l_kq + 0][mm] = av.x;
            As[l_kq + 1][mm] = av.y;
            As[l_kq + 2][mm] = av.z;
            As[l_kq + 3][mm] = av.w;
        }

        // ---- stage B tile: 128 n x 16 k = 512 float4, 2/thread ----
#pragma unroll
        for (int it = 0; it < 2; ++it) {
            int nn = l_row + it * 64;
            float4 bv = *reinterpret_cast<const float4*>(Wsel + (size_t)nn * KH + kb + l_kq);
            Bs[l_kq + 0][nn] = bv.x;
            Bs[l_kq + 1][nn] = bv.y;
            Bs[l_kq + 2][nn] = bv.z;
            Bs[l_kq + 3][nn] = bv.w;
        }
        __syncthreads();

        // ---- compute ----
#pragma unroll
        for (int kk = 0; kk < BK; ++kk) {
            float4 a0 = *reinterpret_cast<const float4*>(&As[kk][tm]);
            float4 a1 = *reinterpret_cast<const float4*>(&As[kk][tm + 4]);
            ulonglong2 b0 = *reinterpret_cast<const ulonglong2*>(&Bs[kk][tn]);
            ulonglong2 b1 = *reinterpret_cast<const ulonglong2*>(&Bs[kk][tn + 4]);

            float a_arr[TM] = {a0.x, a0.y, a0.z, a0.w, a1.x, a1.y, a1.z, a1.w};
#pragma unroll
            for (int i = 0; i < TM; ++i) {
                unsigned long long aa = pack2(a_arr[i]);
                FMA2(acc[i][0], aa, b0.x);
                FMA2(acc[i][1], aa, b0.y);
                FMA2(acc[i][2], aa, b1.x);
                FMA2(acc[i][3], aa, b1.y);
            }
        }
        __syncthreads();
    }

    // ---- epilogue ----
    float bsv[TN];
#pragma unroll
    for (int j = 0; j < TN; ++j) bsv[j] = bias[tn + j];

#pragma unroll
    for (int i = 0; i < TM; ++i) {
        int row = block_m + tm + i;
        if (row >= M) continue;
        float o[TN];
#pragma unroll
        for (int j = 0; j < TN / 2; ++j) {
            unsigned int lo = (unsigned int)(acc[i][j] & 0xFFFFFFFFull);
            unsigned int hi = (unsigned int)(acc[i][j] >> 32);
            o[2 * j + 0] = __uint_as_float(lo) + bsv[2 * j + 0];
            o[2 * j + 1] = __uint_as_float(hi) + bsv[2 * j + 1];
        }
        if (RELU) {
#pragma unroll
            for (int j = 0; j < TN; ++j) o[j] = fmaxf(o[j], 0.f);
        }
        float4* po = reinterpret_cast<float4*>(out + (size_t)row * HID + tn);
        po[0] = make_float4(o[0], o[1], o[2], o[3]);
        po[1] = make_float4(o[4], o[5], o[6], o[7]);
    }
}

// ---------------------------------------------------------------------------
extern "C" void kernel_launch(void* const* d_in, const int* in_sizes, int n_in,
                              void* d_out, int out_size) {
    const float* x   = (const float*)d_in[0];
    const int*   ei  = (const int*)  d_in[1];
    const float* Wl1 = (const float*)d_in[2];
    const float* bl1 = (const float*)d_in[3];
    const float* Wr1 = (const float*)d_in[4];
    const float* Wl2 = (const float*)d_in[5];
    const float* bl2 = (const float*)d_in[6];
    const float* Wr2 = (const float*)d_in[7];
    float* out = (float*)d_out;

    const int E = in_sizes[1] / 2;
    const int M = N_NODES;

    float *agg1, *h, *agg2, *cnt;
    cudaGetSymbolAddress((void**)&agg1, g_agg1);
    cudaGetSymbolAddress((void**)&h,    g_h);
    cudaGetSymbolAddress((void**)&agg2, g_agg2);
    cudaGetSymbolAddress((void**)&cnt,  g_cnt);

    const int gemm_blocks = (M + 127) / 128;

    zero_agg1_cnt<<<(N_NODES * F_IN / 4 + 255) / 256, 256>>>();
    scatter1<<<((long)E * 16 + 255) / 256, 256>>>(
        reinterpret_cast<const float4*>(x), ei, E);
    inv_cnt<<<(N_NODES + 255) / 256, 256>>>();
    sage_gemm<F_IN, true><<<gemm_blocks, 256>>>(agg1, x, cnt, Wl1, Wr1, bl1, h, M);
    zero_agg2<<<(N_NODES * HID / 4 + 255) / 256, 256>>>();
    scatter2<<<((long)E * 32 + 255) / 256, 256>>>(ei, E);
    sage_gemm<HID, false><<<gemm_blocks, 256>>>(agg2, h, cnt, Wl2, Wr2, bl2, out, M);
}

// round 3
// speedup vs baseline: 1.9470x; 1.5193x over previous
#include <cuda_runtime.h>
#include <cuda_bf16.h>

#define N_NODES 100000
#define F_IN    64
#define HID     128
#define E_MAX   1700000
#define SCAN_BLK 512
#define NB ((N_NODES + SCAN_BLK - 1) / SCAN_BLK)   // 196

// Scratch (device globals — no runtime allocation)
__device__ float g_agg1[N_NODES * F_IN];   // mean-aggregated x
__device__ float g_h   [N_NODES * HID];    // layer-1 output
__device__ float g_agg2[N_NODES * HID];    // mean-aggregated h
__device__ int   g_deg [N_NODES];
__device__ int   g_off [N_NODES + 1];
__device__ int   g_cur [N_NODES];
__device__ int   g_bsum[NB];
__device__ int   g_bbase[NB];
__device__ int   g_csr [E_MAX];            // src list grouped by dst

// ---------------------------------------------------------------------------
__device__ __forceinline__ unsigned long long pack2(float f) {
    unsigned long long r;
    unsigned int u = __float_as_uint(f);
    asm("mov.b64 %0, {%1, %1};" : "=l"(r) : "r"(u));
    return r;
}
#define FMA2(d, a, b) \
    asm("fma.rn.f32x2 %0, %1, %2, %0;" : "+l"(d) : "l"(a), "l"(b))

// ---------------------------------------------------------------------------
// CSR build
// ---------------------------------------------------------------------------
__global__ void zero_deg() {
    int i = blockIdx.x * blockDim.x + threadIdx.x;
    if (i < N_NODES) g_deg[i] = 0;
}

__global__ void hist(const int* __restrict__ ei, int E) {
    int e = blockIdx.x * blockDim.x + threadIdx.x;
    if (e < E) atomicAdd(&g_deg[__ldg(ei + E + e)], 1);
}

__global__ void scan1() {
    __shared__ int s[SCAN_BLK];
    int t = threadIdx.x, b = blockIdx.x;
    int i = b * SCAN_BLK + t;
    int v = (i < N_NODES) ? g_deg[i] : 0;
    s[t] = v;
    __syncthreads();
#pragma unroll
    for (int off = 1; off < SCAN_BLK; off <<= 1) {
        int add = (t >= off) ? s[t - off] : 0;
        __syncthreads();
        if (t >= off) s[t] += add;
        __syncthreads();
    }
    if (i < N_NODES) g_off[i] = s[t] - v;     // exclusive
    if (t == SCAN_BLK - 1) g_bsum[b] = s[t];
}

__global__ void scan2() {   // single block of 256
    __shared__ int s[256];
    int t = threadIdx.x;
    int v = (t < NB) ? g_bsum[t] : 0;
    s[t] = v;
    __syncthreads();
#pragma unroll
    for (int off = 1; off < 256; off <<= 1) {
        int add = (t >= off) ? s[t - off] : 0;
        __syncthreads();
        if (t >= off) s[t] += add;
        __syncthreads();
    }
    if (t < NB) g_bbase[t] = s[t] - v;        // exclusive
}

__global__ void scan3(int E) {
    int i = blockIdx.x * blockDim.x + threadIdx.x;
    if (i < N_NODES) {
        int o = g_off[i] + g_bbase[i / SCAN_BLK];
        g_off[i] = o;
        g_cur[i] = o;
    }
    if (i == 0) g_off[N_NODES] = E;
}

__global__ void fill(const int* __restrict__ ei, int E) {
    int e = blockIdx.x * blockDim.x + threadIdx.x;
    if (e >= E) return;
    int src = __ldg(ei + e);
    int dst = __ldg(ei + E + e);
    int pos = atomicAdd(&g_cur[dst], 1);
    g_csr[pos] = src;
}

// ---------------------------------------------------------------------------
// Gather-reduce (mean): FQ float4-chunks per node, one thread per chunk
// ---------------------------------------------------------------------------
template <int FQ>
__global__ void gather_mean(const float4* __restrict__ src4,
                            float4* __restrict__ out4) {
    int idx = blockIdx.x * blockDim.x + threadIdx.x;
    int n = idx / FQ;
    if (n >= N_NODES) return;
    int q = idx % FQ;
    int s  = g_off[n];
    int e2 = g_off[n + 1];
    float4 acc = make_float4(0.f, 0.f, 0.f, 0.f);
    int i = s;
    for (; i + 4 <= e2; i += 4) {
        int s0 = g_csr[i], s1 = g_csr[i + 1], s2 = g_csr[i + 2], s3 = g_csr[i + 3];
        float4 v0 = __ldg(src4 + (size_t)s0 * FQ + q);
        float4 v1 = __ldg(src4 + (size_t)s1 * FQ + q);
        float4 v2 = __ldg(src4 + (size_t)s2 * FQ + q);
        float4 v3 = __ldg(src4 + (size_t)s3 * FQ + q);
        acc.x += v0.x + v1.x + v2.x + v3.x;
        acc.y += v0.y + v1.y + v2.y + v3.y;
        acc.z += v0.z + v1.z + v2.z + v3.z;
        acc.w += v0.w + v1.w + v2.w + v3.w;
    }
    for (; i < e2; ++i) {
        float4 v = __ldg(src4 + (size_t)g_csr[i] * FQ + q);
        acc.x += v.x; acc.y += v.y; acc.z += v.z; acc.w += v.w;
    }
    float inv = 1.0f / fmaxf((float)(e2 - s), 1.0f);
    acc.x *= inv; acc.y *= inv; acc.z *= inv; acc.w *= inv;
    out4[(size_t)n * FQ + q] = acc;
}

// ---------------------------------------------------------------------------
// Fused SAGE GEMM, BM=128 BN=128 BK=16, 256 thr, 8x8/thread, f32x2 FMAs,
// global->register prefetch pipeline.
//   out[m] = Mean[m] @ WL^T + X[m] @ WR^T + bias   (opt. ReLU)
// ---------------------------------------------------------------------------
template <int KH, bool RELU>
__global__ void __launch_bounds__(256)
sage_gemm(const float* __restrict__ Amean,  // [M, KH] mean aggregate
          const float* __restrict__ X,      // [M, KH] root features
          const float* __restrict__ WL,     // [128, KH]
          const float* __restrict__ WR,     // [128, KH]
          const float* __restrict__ bias,   // [128]
          float* __restrict__ out,          // [M, 128]
          int M) {
    constexpr int BM = 128, BN = 128, BK = 16, TM = 8, TN = 8;
    constexpr int K  = 2 * KH;
    constexpr int NT = K / BK;
    constexpr int LDA = BM + 4;
    constexpr int LDB = BN + 4;

    __shared__ float As[BK][LDA];
    __shared__ float Bs[BK][LDB];

    const int tid     = threadIdx.x;
    const int block_m = blockIdx.x * BM;

    const int tn = (tid & 15) * TN;
    const int tm = (tid >> 4) * TM;

    const int l_row = tid >> 2;          // 0..63 (+64 on second iter)
    const int l_kq  = (tid & 3) * 4;

    const int a_row0 = block_m + l_row;
    const int a_row1 = block_m + l_row + 64;
    const bool ok0 = a_row0 < M;
    const bool ok1 = a_row1 < M;

    unsigned long long acc[TM][TN / 2];
#pragma unroll
    for (int i = 0; i < TM; ++i)
#pragma unroll
        for (int j = 0; j < TN / 2; ++j) acc[i][j] = 0ull;

    float4 pa0, pa1, pb0, pb1;

    auto load_tile = [&](int kt, float4& a0, float4& a1, float4& b0, float4& b1) {
        const bool  first = (kt * BK < KH);
        const int   kb    = first ? kt * BK : kt * BK - KH;
        const float* Asrc = first ? Amean : X;
        const float* Wsel = first ? WL : WR;
        a0 = make_float4(0.f, 0.f, 0.f, 0.f);
        a1 = a0;
        if (ok0) a0 = *reinterpret_cast<const float4*>(Asrc + (size_t)a_row0 * KH + kb + l_kq);
        if (ok1) a1 = *reinterpret_cast<const float4*>(Asrc + (size_t)a_row1 * KH + kb + l_kq);
        b0 = *reinterpret_cast<const float4*>(Wsel + (size_t)l_row * KH + kb + l_kq);
        b1 = *reinterpret_cast<const float4*>(Wsel + (size_t)(l_row + 64) * KH + kb + l_kq);
    };

    load_tile(0, pa0, pa1, pb0, pb1);

    for (int kt = 0; kt < NT; ++kt) {
        // store staged regs -> smem
        As[l_kq + 0][l_row]      = pa0.x;
        As[l_kq + 1][l_row]      = pa0.y;
        As[l_kq + 2][l_row]      = pa0.z;
        As[l_kq + 3][l_row]      = pa0.w;
        As[l_kq + 0][l_row + 64] = pa1.x;
        As[l_kq + 1][l_row + 64] = pa1.y;
        As[l_kq + 2][l_row + 64] = pa1.z;
        As[l_kq + 3][l_row + 64] = pa1.w;
        Bs[l_kq + 0][l_row]      = pb0.x;
        Bs[l_kq + 1][l_row]      = pb0.y;
        Bs[l_kq + 2][l_row]      = pb0.z;
        Bs[l_kq + 3][l_row]      = pb0.w;
        Bs[l_kq + 0][l_row + 64] = pb1.x;
        Bs[l_kq + 1][l_row + 64] = pb1.y;
        Bs[l_kq + 2][l_row + 64] = pb1.z;
        Bs[l_kq + 3][l_row + 64] = pb1.w;
        __syncthreads();

        // issue next tile's global loads (latency hidden by compute below)
        if (kt + 1 < NT) load_tile(kt + 1, pa0, pa1, pb0, pb1);

#pragma unroll
        for (int kk = 0; kk < BK; ++kk) {
            float4 a0 = *reinterpret_cast<const float4*>(&As[kk][tm]);
            float4 a1 = *reinterpret_cast<const float4*>(&As[kk][tm + 4]);
            ulonglong2 b0 = *reinterpret_cast<const ulonglong2*>(&Bs[kk][tn]);
            ulonglong2 b1 = *reinterpret_cast<const ulonglong2*>(&Bs[kk][tn + 4]);
            float a_arr[TM] = {a0.x, a0.y, a0.z, a0.w, a1.x, a1.y, a1.z, a1.w};
#pragma unroll
            for (int i = 0; i < TM; ++i) {
                unsigned long long aa = pack2(a_arr[i]);
                FMA2(acc[i][0], aa, b0.x);
                FMA2(acc[i][1], aa, b0.y);
                FMA2(acc[i][2], aa, b1.x);
                FMA2(acc[i][3], aa, b1.y);
            }
        }
        __syncthreads();
    }

    // epilogue
    float bsv[TN];
#pragma unroll
    for (int j = 0; j < TN; ++j) bsv[j] = bias[tn + j];

#pragma unroll
    for (int i = 0; i < TM; ++i) {
        int row = block_m + tm + i;
        if (row >= M) continue;
        float o[TN];
#pragma unroll
        for (int j = 0; j < TN / 2; ++j) {
            unsigned int lo = (unsigned int)(acc[i][j] & 0xFFFFFFFFull);
            unsigned int hi = (unsigned int)(acc[i][j] >> 32);
            o[2 * j + 0] = __uint_as_float(lo) + bsv[2 * j + 0];
            o[2 * j + 1] = __uint_as_float(hi) + bsv[2 * j + 1];
        }
        if (RELU) {
#pragma unroll
            for (int j = 0; j < TN; ++j) o[j] = fmaxf(o[j], 0.f);
        }
        float4* po = reinterpret_cast<float4*>(out + (size_t)row * HID + tn);
        po[0] = make_float4(o[0], o[1], o[2], o[3]);
        po[1] = make_float4(o[4], o[5], o[6], o[7]);
    }
}

// ---------------------------------------------------------------------------
extern "C" void kernel_launch(void* const* d_in, const int* in_sizes, int n_in,
                              void* d_out, int out_size) {
    const float* x   = (const float*)d_in[0];
    const int*   ei  = (const int*)  d_in[1];
    const float* Wl1 = (const float*)d_in[2];
    const float* bl1 = (const float*)d_in[3];
    const float* Wr1 = (const float*)d_in[4];
    const float* Wl2 = (const float*)d_in[5];
    const float* bl2 = (const float*)d_in[6];
    const float* Wr2 = (const float*)d_in[7];
    float* out = (float*)d_out;

    const int E = in_sizes[1] / 2;
    const int M = N_NODES;

    float *agg1, *h, *agg2;
    cudaGetSymbolAddress((void**)&agg1, g_agg1);
    cudaGetSymbolAddress((void**)&h,    g_h);
    cudaGetSymbolAddress((void**)&agg2, g_agg2);

    const int gemm_blocks = (M + 127) / 128;

    // CSR build (reused by both layers)
    zero_deg<<<(N_NODES + 255) / 256, 256>>>();
    hist<<<(E + 255) / 256, 256>>>(ei, E);
    scan1<<<NB, SCAN_BLK>>>();
    scan2<<<1, 256>>>();
    scan3<<<(N_NODES + 255) / 256, 256>>>(E);
    fill<<<(E + 255) / 256, 256>>>(ei, E);

    // Layer 1
    gather_mean<16><<<((long)M * 16 + 255) / 256, 256>>>(
        reinterpret_cast<const float4*>(x),
        reinterpret_cast<float4*>(agg1));
    sage_gemm<F_IN, true><<<gemm_blocks, 256>>>(agg1, x, Wl1, Wr1, bl1, h, M);

    // Layer 2
    gather_mean<32><<<((long)M * 32 + 255) / 256, 256>>>(
        reinterpret_cast<const float4*>(h),
        reinterpret_cast<float4*>(agg2));
    sage_gemm<HID, false><<<gemm_blocks, 256>>>(agg2, h, Wl2, Wr2, bl2, out, M);
}

// round 5
// speedup vs baseline: 2.5102x; 1.2893x over previous
#include <cuda_runtime.h>
#include <cuda_bf16.h>
#include <cstdint>

#define N_NODES 100000
#define F_IN    64
#define HID     128
#define E_MAX   1700000
#define SCAN_BLK 512
#define NB ((N_NODES + SCAN_BLK - 1) / SCAN_BLK)   // 196

// ---------------------------------------------------------------------------
// Scratch (device globals — no runtime allocation)
// ---------------------------------------------------------------------------
__device__ __align__(16) __nv_bfloat16 g_A1hi[N_NODES * 128];  // [mean_x | x] hi
__device__ __align__(16) __nv_bfloat16 g_A1lo[N_NODES * 128];
__device__ __align__(16) __nv_bfloat16 g_A2hi[N_NODES * 256];  // [mean_h | h] hi
__device__ __align__(16) __nv_bfloat16 g_A2lo[N_NODES * 256];
__device__ __align__(16) float g_h[N_NODES * HID];             // layer-1 out fp32
__device__ __align__(16) __nv_bfloat16 g_B1hi[128 * 128];      // [Wl1 | Wr1] rows n, k-contig
__device__ __align__(16) __nv_bfloat16 g_B1lo[128 * 128];
__device__ __align__(16) __nv_bfloat16 g_B2hi[128 * 256];
__device__ __align__(16) __nv_bfloat16 g_B2lo[128 * 256];
__device__ int g_deg [N_NODES];
__device__ int g_off [N_NODES + 1];
__device__ int g_cur [N_NODES];
__device__ int g_bsum[NB];
__device__ int g_bbase[NB];
__device__ int g_csr [E_MAX];

// ---------------------------------------------------------------------------
__device__ __forceinline__ uint32_t smem_u32(const void* p) {
    return (uint32_t)__cvta_generic_to_shared(p);
}

#define CP_ASYNC16(dst, src) \
    asm volatile("cp.async.cg.shared.global [%0], [%1], 16;" :: "r"(dst), "l"(src))
#define CP_COMMIT() asm volatile("cp.async.commit_group;" ::: "memory")
#define CP_WAIT(n)  asm volatile("cp.async.wait_group %0;" :: "n"(n) : "memory")

#define LDSM4(r0, r1, r2, r3, addr) \
    asm volatile("ldmatrix.sync.aligned.m8n8.x4.shared.b16 {%0,%1,%2,%3}, [%4];" \
                 : "=r"(r0), "=r"(r1), "=r"(r2), "=r"(r3) : "r"(addr))

#define MMA16816(d, a, b0, b1) \
    asm volatile("mma.sync.aligned.m16n8k16.row.col.f32.bf16.bf16.f32 " \
                 "{%0,%1,%2,%3}, {%4,%5,%6,%7}, {%8,%9}, {%0,%1,%2,%3};" \
                 : "+f"((d)[0]), "+f"((d)[1]), "+f"((d)[2]), "+f"((d)[3]) \
                 : "r"((a)[0]), "r"((a)[1]), "r"((a)[2]), "r"((a)[3]), \
                   "r"(b0), "r"(b1))

__device__ __forceinline__ void split_bf16(float v, __nv_bfloat16& hi, __nv_bfloat16& lo) {
    hi = __float2bfloat16(v);
    lo = __float2bfloat16(v - __bfloat162float(hi));
}

// ---------------------------------------------------------------------------
// CSR build
// ---------------------------------------------------------------------------
__global__ void zero_deg() {
    int i = blockIdx.x * blockDim.x + threadIdx.x;
    if (i < N_NODES) g_deg[i] = 0;
}
__global__ void hist(const int* __restrict__ ei, int E) {
    int e = blockIdx.x * blockDim.x + threadIdx.x;
    if (e < E) atomicAdd(&g_deg[__ldg(ei + E + e)], 1);
}
__global__ void scan1() {
    __shared__ int s[SCAN_BLK];
    int t = threadIdx.x, b = blockIdx.x;
    int i = b * SCAN_BLK + t;
    int v = (i < N_NODES) ? g_deg[i] : 0;
    s[t] = v;
    __syncthreads();
#pragma unroll
    for (int off = 1; off < SCAN_BLK; off <<= 1) {
        int add = (t >= off) ? s[t - off] : 0;
        __syncthreads();
        if (t >= off) s[t] += add;
        __syncthreads();
    }
    if (i < N_NODES) g_off[i] = s[t] - v;
    if (t == SCAN_BLK - 1) g_bsum[b] = s[t];
}
__global__ void scan2() {
    __shared__ int s[256];
    int t = threadIdx.x;
    int v = (t < NB) ? g_bsum[t] : 0;
    s[t] = v;
    __syncthreads();
#pragma unroll
    for (int off = 1; off < 256; off <<= 1) {
        int add = (t >= off) ? s[t - off] : 0;
        __syncthreads();
        if (t >= off) s[t] += add;
        __syncthreads();
    }
    if (t < NB) g_bbase[t] = s[t] - v;
}
__global__ void scan3(int E) {
    int i = blockIdx.x * blockDim.x + threadIdx.x;
    if (i < N_NODES) {
        int o = g_off[i] + g_bbase[i / SCAN_BLK];
        g_off[i] = o;
        g_cur[i] = o;
    }
    if (i == 0) g_off[N_NODES] = E;
}
__global__ void fill(const int* __restrict__ ei, int E) {
    int e = blockIdx.x * blockDim.x + threadIdx.x;
    if (e >= E) return;
    int src = __ldg(ei + e);
    int dst = __ldg(ei + E + e);
    int pos = atomicAdd(&g_cur[dst], 1);
    g_csr[pos] = src;
}

// ---------------------------------------------------------------------------
// Weight convert: fp32 [WL|WR] -> bf16 hi/lo, rows n, virtual-k contiguous
// ---------------------------------------------------------------------------
__global__ void wconv(const float* __restrict__ WL1, const float* __restrict__ WR1,
                      const float* __restrict__ WL2, const float* __restrict__ WR2) {
    int idx = blockIdx.x * blockDim.x + threadIdx.x;
    if (idx < 128 * 128) {                      // layer 1, K = 128
        int n = idx >> 7, k = idx & 127;
        float v = (k < 64) ? __ldg(WL1 + n * 64 + k) : __ldg(WR1 + n * 64 + (k - 64));
        __nv_bfloat16 hi, lo;
        split_bf16(v, hi, lo);
        g_B1hi[idx] = hi;
        g_B1lo[idx] = lo;
    } else if (idx < 128 * 128 + 128 * 256) {   // layer 2, K = 256
        int j = idx - 128 * 128;
        int n = j >> 8, k = j & 255;
        float v = (k < 128) ? __ldg(WL2 + n * 128 + k) : __ldg(WR2 + n * 128 + (k - 128));
        __nv_bfloat16 hi, lo;
        split_bf16(v, hi, lo);
        g_B2hi[j] = hi;
        g_B2lo[j] = lo;
    }
}

// x -> hi/lo into A1 cols 64..127
__global__ void convert_x(const float4* __restrict__ x4) {
    int idx = blockIdx.x * blockDim.x + threadIdx.x;
    if (idx >= N_NODES * 16) return;
    int n = idx >> 4, q = idx & 15;
    float4 v = __ldg(x4 + idx);
    __nv_bfloat16 h0, l0, h1, l1, h2, l2, h3, l3;
    split_bf16(v.x, h0, l0); split_bf16(v.y, h1, l1);
    split_bf16(v.z, h2, l2); split_bf16(v.w, h3, l3);
    size_t base = (size_t)n * 128 + 64 + q * 4;
    __nv_bfloat162* ph = reinterpret_cast<__nv_bfloat162*>(g_A1hi + base);
    __nv_bfloat162* pl = reinterpret_cast<__nv_bfloat162*>(g_A1lo + base);
    __nv_bfloat162 a; a.x = h0; a.y = h1; ph[0] = a;
    a.x = h2; a.y = h3; ph[1] = a;
    a.x = l0; a.y = l1; pl[0] = a;
    a.x = l2; a.y = l3; pl[1] = a;
}

// ---------------------------------------------------------------------------
// Gather-reduce (mean) -> bf16 hi/lo into A buffer cols [0, FQ*4)
// ---------------------------------------------------------------------------
template <int FQ, int AK>
__global__ void gather_mean(const float4* __restrict__ src4,
                            __nv_bfloat16* __restrict__ ahi,
                            __nv_bfloat16* __restrict__ alo) {
    int idx = blockIdx.x * blockDim.x + threadIdx.x;
    int n = idx / FQ;
    if (n >= N_NODES) return;
    int q = idx % FQ;
    int s  = g_off[n];
    int e2 = g_off[n + 1];
    float4 acc = make_float4(0.f, 0.f, 0.f, 0.f);
    int i = s;
    for (; i + 4 <= e2; i += 4) {
        int s0 = g_csr[i], s1 = g_csr[i + 1], s2 = g_csr[i + 2], s3 = g_csr[i + 3];
        float4 v0 = __ldg(src4 + (size_t)s0 * FQ + q);
        float4 v1 = __ldg(src4 + (size_t)s1 * FQ + q);
        float4 v2 = __ldg(src4 + (size_t)s2 * FQ + q);
        float4 v3 = __ldg(src4 + (size_t)s3 * FQ + q);
        acc.x += v0.x + v1.x + v2.x + v3.x;
        acc.y += v0.y + v1.y + v2.y + v3.y;
        acc.z += v0.z + v1.z + v2.z + v3.z;
        acc.w += v0.w + v1.w + v2.w + v3.w;
    }
    for (; i < e2; ++i) {
        float4 v = __ldg(src4 + (size_t)g_csr[i] * FQ + q);
        acc.x += v.x; acc.y += v.y; acc.z += v.z; acc.w += v.w;
    }
    float inv = 1.0f / fmaxf((float)(e2 - s), 1.0f);
    acc.x *= inv; acc.y *= inv; acc.z *= inv; acc.w *= inv;

    __nv_bfloat16 h0, l0, h1, l1, h2, l2, h3, l3;
    split_bf16(acc.x, h0, l0); split_bf16(acc.y, h1, l1);
    split_bf16(acc.z, h2, l2); split_bf16(acc.w, h3, l3);
    size_t base = (size_t)n * AK + q * 4;
    __nv_bfloat162* ph = reinterpret_cast<__nv_bfloat162*>(ahi + base);
    __nv_bfloat162* pl = reinterpret_cast<__nv_bfloat162*>(alo + base);
    __nv_bfloat162 a; a.x = h0; a.y = h1; ph[0] = a;
    a.x = h2; a.y = h3; ph[1] = a;
    a.x = l0; a.y = l1; pl[0] = a;
    a.x = l2; a.y = l3; pl[1] = a;
}

// ---------------------------------------------------------------------------
// mma.sync bf16 hi/lo-compensated SAGE GEMM.
//   BM=128 BN=128 BK=64, 8 warps (4m x 2n), warp tile 32x64.
//   Virtual K loop = 3 segments: Ahi*Bhi, Ahi*Blo, Alo*Bhi.
//   cp.async double-buffered smem, XOR-swizzled 16B chunks for ldmatrix.
// ---------------------------------------------------------------------------
template <int K, bool LAYER1>
__global__ void __launch_bounds__(256)
sage_gemm_mma(const __nv_bfloat16* __restrict__ Ahi,
              const __nv_bfloat16* __restrict__ Alo,
              const __nv_bfloat16* __restrict__ Bhi,
              const __nv_bfloat16* __restrict__ Blo,
              const float* __restrict__ bias,
              float* __restrict__ outF,
              __nv_bfloat16* __restrict__ a2hi,
              __nv_bfloat16* __restrict__ a2lo,
              int M) {
    constexpr int BK     = 64;
    constexpr int KSTEPS = K / BK;
    constexpr int NS     = 3 * KSTEPS;
    constexpr int STAGE  = 32768;          // A 16KB + B 16KB

    extern __shared__ char smem[];

    const int tid     = threadIdx.x;
    const int block_m = blockIdx.x * 128;
    const int warp    = tid >> 5;
    const int lane    = tid & 31;
    const int wm      = warp & 3;          // 0..3 -> m offset *32
    const int wn      = warp >> 2;         // 0..1 -> n offset *64

    // stage loader: 1024 A-chunks + 1024 B-chunks of 16B, 4+4 per thread
    auto issue_stage = [&](int s) {
        const int seg = s / KSTEPS;
        const int k0  = (s % KSTEPS) * BK;
        const __nv_bfloat16* Aseg = (seg == 2) ? Alo : Ahi;
        const __nv_bfloat16* Bseg = (seg == 1) ? Blo : Bhi;
        char* sA = smem + (s & 1) * STAGE;
        char* sB = sA + 16384;
#pragma unroll
        for (int j = 0; j < 4; ++j) {
            int c   = tid * 4 + j;
            int row = c >> 3, ch = c & 7;
            int grow = block_m + row;
            if (grow >= M) grow = M - 1;
            const char* src = reinterpret_cast<const char*>(Aseg + (size_t)grow * K + k0) + ch * 16;
            uint32_t dst = smem_u32(sA + row * 128 + ((ch ^ (row & 7)) << 4));
            CP_ASYNC16(dst, src);
        }
#pragma unroll
        for (int j = 0; j < 4; ++j) {
            int c   = tid * 4 + j;
            int row = c >> 3, ch = c & 7;
            const char* src = reinterpret_cast<const char*>(Bseg + (size_t)row * K + k0) + ch * 16;
            uint32_t dst = smem_u32(sB + row * 128 + ((ch ^ (row & 7)) << 4));
            CP_ASYNC16(dst, src);
        }
        CP_COMMIT();
    };

    float d[2][8][4];
#pragma unroll
    for (int i = 0; i < 2; ++i)
#pragma unroll
        for (int j = 0; j < 8; ++j)
#pragma unroll
            for (int q = 0; q < 4; ++q) d[i][j][q] = 0.f;

    issue_stage(0);

    for (int s = 0; s < NS; ++s) {
        if (s + 1 < NS) {
            issue_stage(s + 1);
            CP_WAIT(1);
        } else {
            CP_WAIT(0);
        }
        __syncthreads();

        const uint32_t sA = smem_u32(smem + (s & 1) * STAGE);
        const uint32_t sB = sA + 16384;

#pragma unroll
        for (int kk = 0; kk < 4; ++kk) {
            uint32_t a[2][4];
#pragma unroll
            for (int mt = 0; mt < 2; ++mt) {
                int row = wm * 32 + mt * 16 + (lane & 15);
                int ch  = kk * 2 + (lane >> 4);
                uint32_t addr = sA + row * 128 + ((ch ^ (row & 7)) << 4);
                LDSM4(a[mt][0], a[mt][1], a[mt][2], a[mt][3], addr);
            }
            uint32_t b[4][4];
#pragma unroll
            for (int nt2 = 0; nt2 < 4; ++nt2) {
                int row = wn * 64 + nt2 * 16 + (lane & 15);
                int ch  = kk * 2 + (lane >> 4);
                uint32_t addr = sB + row * 128 + ((ch ^ (row & 7)) << 4);
                LDSM4(b[nt2][0], b[nt2][1], b[nt2][2], b[nt2][3], addr);
            }
#pragma unroll
            for (int mt = 0; mt < 2; ++mt)
#pragma unroll
                for (int nt = 0; nt < 8; ++nt) {
                    int nt2 = nt >> 1, o = nt & 1;
                    MMA16816(d[mt][nt], a[mt], b[nt2][o], b[nt2][o + 2]);
                }
        }
        __syncthreads();
    }

    // ---- epilogue ----
    const int r0base = block_m + wm * 32 + (lane >> 2);
    const int cbase  = wn * 64 + (lane & 3) * 2;
#pragma unroll
    for (int mt = 0; mt < 2; ++mt) {
#pragma unroll
        for (int nt = 0; nt < 8; ++nt) {
            int c = cbase + nt * 8;
            float b0 = __ldg(bias + c);
            float b1 = __ldg(bias + c + 1);
#pragma unroll
            for (int half = 0; half < 2; ++half) {
                int row = r0base + mt * 16 + half * 8;
                if (row >= M) continue;
                float o0 = d[mt][nt][half * 2 + 0] + b0;
                float o1 = d[mt][nt][half * 2 + 1] + b1;
                if (LAYER1) { o0 = fmaxf(o0, 0.f); o1 = fmaxf(o1, 0.f); }
                float2* po = reinterpret_cast<float2*>(outF + (size_t)row * 128 + c);
                *po = make_float2(o0, o1);
                if (LAYER1) {
                    __nv_bfloat16 h0, l0, h1, l1;
                    split_bf16(o0, h0, l0);
                    split_bf16(o1, h1, l1);
                    size_t ab = (size_t)row * 256 + 128 + c;
                    __nv_bfloat162 v;
                    v.x = h0; v.y = h1;
                    *reinterpret_cast<__nv_bfloat162*>(a2hi + ab) = v;
                    v.x = l0; v.y = l1;
                    *reinterpret_cast<__nv_bfloat162*>(a2lo + ab) = v;
                }
            }
        }
    }
}

// ---------------------------------------------------------------------------
extern "C" void kernel_launch(void* const* d_in, const int* in_sizes, int n_in,
                              void* d_out, int out_size) {
    const float* x   = (const float*)d_in[0];
    const int*   ei  = (const int*)  d_in[1];
    const float* Wl1 = (const float*)d_in[2];
    const float* bl1 = (const float*)d_in[3];
    const float* Wr1 = (const float*)d_in[4];
    const float* Wl2 = (const float*)d_in[5];
    const float* bl2 = (const float*)d_in[6];
    const float* Wr2 = (const float*)d_in[7];
    float* out = (float*)d_out;

    const int E = in_sizes[1] / 2;
    const int M = N_NODES;

    __nv_bfloat16 *a1hi, *a1lo, *a2hi, *a2lo, *b1hi, *b1lo, *b2hi, *b2lo;
    float* h;
    cudaGetSymbolAddress((void**)&a1hi, g_A1hi);
    cudaGetSymbolAddress((void**)&a1lo, g_A1lo);
    cudaGetSymbolAddress((void**)&a2hi, g_A2hi);
    cudaGetSymbolAddress((void**)&a2lo, g_A2lo);
    cudaGetSymbolAddress((void**)&b1hi, g_B1hi);
    cudaGetSymbolAddress((void**)&b1lo, g_B1lo);
    cudaGetSymbolAddress((void**)&b2hi, g_B2hi);
    cudaGetSymbolAddress((void**)&b2lo, g_B2lo);
    cudaGetSymbolAddress((void**)&h,    g_h);

    static bool attr_done = false;
    if (!attr_done) {
        cudaFuncSetAttribute(sage_gemm_mma<128, true>,
                             cudaFuncAttributeMaxDynamicSharedMemorySize, 65536);
        cudaFuncSetAttribute(sage_gemm_mma<256, false>,
                             cudaFuncAttributeMaxDynamicSharedMemorySize, 65536);
        attr_done = true;
    }

    const int gemm_blocks = (M + 127) / 128;

    // CSR build
    zero_deg<<<(N_NODES + 255) / 256, 256>>>();
    hist<<<(E + 255) / 256, 256>>>(ei, E);
    scan1<<<NB, SCAN_BLK>>>();
    scan2<<<1, 256>>>();
    scan3<<<(N_NODES + 255) / 256, 256>>>(E);
    fill<<<(E + 255) / 256, 256>>>(ei, E);

    // operand prep
    wconv<<<(128 * 128 + 128 * 256 + 255) / 256, 256>>>(Wl1, Wr1, Wl2, Wr2);
    convert_x<<<((long)M * 16 + 255) / 256, 256>>>(
        reinterpret_cast<const float4*>(x));

    // layer 1
    gather_mean<16, 128><<<((long)M * 16 + 255) / 256, 256>>>(
        reinterpret_cast<const float4*>(x), a1hi, a1lo);
    sage_gemm_mma<128, true><<<gemm_blocks, 256, 65536>>>(
        a1hi, a1lo, b1hi, b1lo, bl1, h, a2hi, a2lo, M);

    // layer 2
    gather_mean<32, 256><<<((long)M * 32 + 255) / 256, 256>>>(
        reinterpret_cast<const float4*>(h), a2hi, a2lo);
    sage_gemm_mma<256, false><<<gemm_blocks, 256, 65536>>>(
        a2hi, a2lo, b2hi, b2lo, bl2, out, nullptr, nullptr, M);
}

// round 6
// speedup vs baseline: 2.6797x; 1.0675x over previous
#include <cuda_runtime.h>
#include <cuda_bf16.h>
#include <cuda_fp16.h>
#include <cstdint>

#define N_NODES 100000
#define F_IN    64
#define HID     128
#define E_MAX   1700000
#define SCAN_BLK 512
#define NB ((N_NODES + SCAN_BLK - 1) / SCAN_BLK)   // 196

// ---------------------------------------------------------------------------
// Scratch (device globals — no runtime allocation)
// ---------------------------------------------------------------------------
__device__ __align__(16) __nv_bfloat16 g_A1hi[N_NODES * 128];  // [mean_x | x] hi
__device__ __align__(16) __nv_bfloat16 g_A1lo[N_NODES * 128];
__device__ __align__(16) __nv_bfloat16 g_A2hi[N_NODES * 256];  // [mean_h | h] hi
__device__ __align__(16) __nv_bfloat16 g_A2lo[N_NODES * 256];
__device__ __align__(16) __half g_hf[N_NODES * HID];           // layer-1 out fp16
__device__ __align__(16) __nv_bfloat16 g_B1hi[128 * 128];      // [Wl1 | Wr1] rows n, k-contig
__device__ __align__(16) __nv_bfloat16 g_B1lo[128 * 128];
__device__ __align__(16) __nv_bfloat16 g_B2hi[128 * 256];
__device__ __align__(16) __nv_bfloat16 g_B2lo[128 * 256];
__device__ int g_deg [N_NODES];
__device__ int g_off [N_NODES + 1];
__device__ int g_cur [N_NODES];
__device__ int g_bsum[NB];
__device__ int g_bbase[NB];
__device__ int g_csr [E_MAX];

// ---------------------------------------------------------------------------
__device__ __forceinline__ uint32_t smem_u32(const void* p) {
    return (uint32_t)__cvta_generic_to_shared(p);
}

#define CP_ASYNC16(dst, src) \
    asm volatile("cp.async.cg.shared.global [%0], [%1], 16;" :: "r"(dst), "l"(src))
#define CP_COMMIT() asm volatile("cp.async.commit_group;" ::: "memory")
#define CP_WAIT(n)  asm volatile("cp.async.wait_group %0;" :: "n"(n) : "memory")

#define LDSM4(r0, r1, r2, r3, addr) \
    asm volatile("ldmatrix.sync.aligned.m8n8.x4.shared.b16 {%0,%1,%2,%3}, [%4];" \
                 : "=r"(r0), "=r"(r1), "=r"(r2), "=r"(r3) : "r"(addr))

#define MMA16816(d, a, b0, b1) \
    asm volatile("mma.sync.aligned.m16n8k16.row.col.f32.bf16.bf16.f32 " \
                 "{%0,%1,%2,%3}, {%4,%5,%6,%7}, {%8,%9}, {%0,%1,%2,%3};" \
                 : "+f"((d)[0]), "+f"((d)[1]), "+f"((d)[2]), "+f"((d)[3]) \
                 : "r"((a)[0]), "r"((a)[1]), "r"((a)[2]), "r"((a)[3]), \
                   "r"(b0), "r"(b1))

__device__ __forceinline__ void split_bf16(float v, __nv_bfloat16& hi, __nv_bfloat16& lo) {
    hi = __float2bfloat16(v);
    lo = __float2bfloat16(v - __bfloat162float(hi));
}

// ---------------------------------------------------------------------------
// CSR build
// ---------------------------------------------------------------------------
__global__ void zero_deg() {
    int i = blockIdx.x * blockDim.x + threadIdx.x;
    if (i < N_NODES) g_deg[i] = 0;
}
__global__ void hist(const int* __restrict__ ei, int E) {
    int e = blockIdx.x * blockDim.x + threadIdx.x;
    if (e < E) atomicAdd(&g_deg[__ldg(ei + E + e)], 1);
}
__global__ void scan1() {
    __shared__ int s[SCAN_BLK];
    int t = threadIdx.x, b = blockIdx.x;
    int i = b * SCAN_BLK + t;
    int v = (i < N_NODES) ? g_deg[i] : 0;
    s[t] = v;
    __syncthreads();
#pragma unroll
    for (int off = 1; off < SCAN_BLK; off <<= 1) {
        int add = (t >= off) ? s[t - off] : 0;
        __syncthreads();
        if (t >= off) s[t] += add;
        __syncthreads();
    }
    if (i < N_NODES) g_off[i] = s[t] - v;
    if (t == SCAN_BLK - 1) g_bsum[b] = s[t];
}
__global__ void scan2() {
    __shared__ int s[256];
    int t = threadIdx.x;
    int v = (t < NB) ? g_bsum[t] : 0;
    s[t] = v;
    __syncthreads();
#pragma unroll
    for (int off = 1; off < 256; off <<= 1) {
        int add = (t >= off) ? s[t - off] : 0;
        __syncthreads();
        if (t >= off) s[t] += add;
        __syncthreads();
    }
    if (t < NB) g_bbase[t] = s[t] - v;
}
__global__ void scan3(int E) {
    int i = blockIdx.x * blockDim.x + threadIdx.x;
    if (i < N_NODES) {
        int o = g_off[i] + g_bbase[i / SCAN_BLK];
        g_off[i] = o;
        g_cur[i] = o;
    }
    if (i == 0) g_off[N_NODES] = E;
}
__global__ void fill(const int* __restrict__ ei, int E) {
    int e = blockIdx.x * blockDim.x + threadIdx.x;
    if (e >= E) return;
    int src = __ldg(ei + e);
    int dst = __ldg(ei + E + e);
    int pos = atomicAdd(&g_cur[dst], 1);
    g_csr[pos] = src;
}

// ---------------------------------------------------------------------------
// Weight convert: fp32 [WL|WR] -> bf16 hi/lo, rows n, virtual-k contiguous
// ---------------------------------------------------------------------------
__global__ void wconv(const float* __restrict__ WL1, const float* __restrict__ WR1,
                      const float* __restrict__ WL2, const float* __restrict__ WR2) {
    int idx = blockIdx.x * blockDim.x + threadIdx.x;
    if (idx < 128 * 128) {                      // layer 1, K = 128
        int n = idx >> 7, k = idx & 127;
        float v = (k < 64) ? __ldg(WL1 + n * 64 + k) : __ldg(WR1 + n * 64 + (k - 64));
        __nv_bfloat16 hi, lo;
        split_bf16(v, hi, lo);
        g_B1hi[idx] = hi;
        g_B1lo[idx] = lo;
    } else if (idx < 128 * 128 + 128 * 256) {   // layer 2, K = 256
        int j = idx - 128 * 128;
        int n = j >> 8, k = j & 255;
        float v = (k < 128) ? __ldg(WL2 + n * 128 + k) : __ldg(WR2 + n * 128 + (k - 128));
        __nv_bfloat16 hi, lo;
        split_bf16(v, hi, lo);
        g_B2hi[j] = hi;
        g_B2lo[j] = lo;
    }
}

// x -> hi/lo into A1 cols 64..127
__global__ void convert_x(const float4* __restrict__ x4) {
    int idx = blockIdx.x * blockDim.x + threadIdx.x;
    if (idx >= N_NODES * 16) return;
    int n = idx >> 4, q = idx & 15;
    float4 v = __ldg(x4 + idx);
    __nv_bfloat16 h0, l0, h1, l1, h2, l2, h3, l3;
    split_bf16(v.x, h0, l0); split_bf16(v.y, h1, l1);
    split_bf16(v.z, h2, l2); split_bf16(v.w, h3, l3);
    size_t base = (size_t)n * 128 + 64 + q * 4;
    __nv_bfloat162* ph = reinterpret_cast<__nv_bfloat162*>(g_A1hi + base);
    __nv_bfloat162* pl = reinterpret_cast<__nv_bfloat162*>(g_A1lo + base);
    __nv_bfloat162 a; a.x = h0; a.y = h1; ph[0] = a;
    a.x = h2; a.y = h3; ph[1] = a;
    a.x = l0; a.y = l1; pl[0] = a;
    a.x = l2; a.y = l3; pl[1] = a;
}

// ---------------------------------------------------------------------------
// Layer-1 gather (fp32 x): FQ float4-chunks per node -> bf16 hi/lo mean
// ---------------------------------------------------------------------------
template <int FQ, int AK>
__global__ void gather_mean(const float4* __restrict__ src4,
                            __nv_bfloat16* __restrict__ ahi,
                            __nv_bfloat16* __restrict__ alo) {
    int idx = blockIdx.x * blockDim.x + threadIdx.x;
    int n = idx / FQ;
    if (n >= N_NODES) return;
    int q = idx % FQ;
    int s  = g_off[n];
    int e2 = g_off[n + 1];
    float4 acc = make_float4(0.f, 0.f, 0.f, 0.f);
    int i = s;
    for (; i + 4 <= e2; i += 4) {
        int s0 = g_csr[i], s1 = g_csr[i + 1], s2 = g_csr[i + 2], s3 = g_csr[i + 3];
        float4 v0 = __ldg(src4 + (size_t)s0 * FQ + q);
        float4 v1 = __ldg(src4 + (size_t)s1 * FQ + q);
        float4 v2 = __ldg(src4 + (size_t)s2 * FQ + q);
        float4 v3 = __ldg(src4 + (size_t)s3 * FQ + q);
        acc.x += v0.x + v1.x + v2.x + v3.x;
        acc.y += v0.y + v1.y + v2.y + v3.y;
        acc.z += v0.z + v1.z + v2.z + v3.z;
        acc.w += v0.w + v1.w + v2.w + v3.w;
    }
    for (; i < e2; ++i) {
        float4 v = __ldg(src4 + (size_t)g_csr[i] * FQ + q);
        acc.x += v.x; acc.y += v.y; acc.z += v.z; acc.w += v.w;
    }
    float inv = 1.0f / fmaxf((float)(e2 - s), 1.0f);
    acc.x *= inv; acc.y *= inv; acc.z *= inv; acc.w *= inv;

    __nv_bfloat16 h0, l0, h1, l1, h2, l2, h3, l3;
    split_bf16(acc.x, h0, l0); split_bf16(acc.y, h1, l1);
    split_bf16(acc.z, h2, l2); split_bf16(acc.w, h3, l3);
    size_t base = (size_t)n * AK + q * 4;
    __nv_bfloat162* ph = reinterpret_cast<__nv_bfloat162*>(ahi + base);
    __nv_bfloat162* pl = reinterpret_cast<__nv_bfloat162*>(alo + base);
    __nv_bfloat162 a; a.x = h0; a.y = h1; ph[0] = a;
    a.x = h2; a.y = h3; ph[1] = a;
    a.x = l0; a.y = l1; pl[0] = a;
    a.x = l2; a.y = l3; pl[1] = a;
}

// ---------------------------------------------------------------------------
// Layer-2 gather (fp16 h): 16 threads/node, 16B chunks (8 halfs), fp32 accum
// ---------------------------------------------------------------------------
__global__ void gather_mean_h(const uint4* __restrict__ srcH,
                              __nv_bfloat16* __restrict__ ahi,
                              __nv_bfloat16* __restrict__ alo) {
    int idx = blockIdx.x * blockDim.x + threadIdx.x;
    int n = idx >> 4;
    if (n >= N_NODES) return;
    int q = idx & 15;
    int s  = g_off[n];
    int e2 = g_off[n + 1];

    float acc[8];
#pragma unroll
    for (int j = 0; j < 8; ++j) acc[j] = 0.f;

    auto accum = [&](uint4 v) {
        const __half2* p = reinterpret_cast<const __half2*>(&v);
#pragma unroll
        for (int w = 0; w < 4; ++w) {
            float2 f = __half22float2(p[w]);
            acc[2 * w + 0] += f.x;
            acc[2 * w + 1] += f.y;
        }
    };

    int i = s;
    for (; i + 4 <= e2; i += 4) {
        int s0 = g_csr[i], s1 = g_csr[i + 1], s2 = g_csr[i + 2], s3 = g_csr[i + 3];
        uint4 v0 = __ldg(srcH + (size_t)s0 * 16 + q);
        uint4 v1 = __ldg(srcH + (size_t)s1 * 16 + q);
        uint4 v2 = __ldg(srcH + (size_t)s2 * 16 + q);
        uint4 v3 = __ldg(srcH + (size_t)s3 * 16 + q);
        accum(v0); accum(v1); accum(v2); accum(v3);
    }
    for (; i < e2; ++i)
        accum(__ldg(srcH + (size_t)g_csr[i] * 16 + q));

    float inv = 1.0f / fmaxf((float)(e2 - s), 1.0f);

    __nv_bfloat16 hb[8], lb[8];
#pragma unroll
    for (int j = 0; j < 8; ++j) {
        float m = acc[j] * inv;
        split_bf16(m, hb[j], lb[j]);
    }
    size_t base = (size_t)n * 256 + q * 8;
    uint4 vh, vl;
    __nv_bfloat162* ph = reinterpret_cast<__nv_bfloat162*>(&vh);
    __nv_bfloat162* pl = reinterpret_cast<__nv_bfloat162*>(&vl);
#pragma unroll
    for (int w = 0; w < 4; ++w) {
        __nv_bfloat162 t;
        t.x = hb[2 * w]; t.y = hb[2 * w + 1]; ph[w] = t;
        t.x = lb[2 * w]; t.y = lb[2 * w + 1]; pl[w] = t;
    }
    *reinterpret_cast<uint4*>(ahi + base) = vh;
    *reinterpret_cast<uint4*>(alo + base) = vl;
}

// ---------------------------------------------------------------------------
// mma.sync bf16 hi/lo-compensated SAGE GEMM.
//   BM=128 BN=128 BK=64, 8 warps (4m x 2n), warp tile 32x64.
//   Virtual K loop = 3 segments: Ahi*Bhi, Ahi*Blo, Alo*Bhi.
//   cp.async double-buffered smem, XOR-swizzled 16B chunks for ldmatrix.
// LAYER1: writes h fp16 AND bf16 hi/lo root half into A2 cols 128..255.
// ---------------------------------------------------------------------------
template <int K, bool LAYER1>
__global__ void __launch_bounds__(256)
sage_gemm_mma(const __nv_bfloat16* __restrict__ Ahi,
              const __nv_bfloat16* __restrict__ Alo,
              const __nv_bfloat16* __restrict__ Bhi,
              const __nv_bfloat16* __restrict__ Blo,
              const float* __restrict__ bias,
              float* __restrict__ outF,
              __half* __restrict__ outH,
              __nv_bfloat16* __restrict__ a2hi,
              __nv_bfloat16* __restrict__ a2lo,
              int M) {
    constexpr int BK     = 64;
    constexpr int KSTEPS = K / BK;
    constexpr int NS     = 3 * KSTEPS;
    constexpr int STAGE  = 32768;          // A 16KB + B 16KB

    extern __shared__ char smem[];

    const int tid     = threadIdx.x;
    const int block_m = blockIdx.x * 128;
    const int warp    = tid >> 5;
    const int lane    = tid & 31;
    const int wm      = warp & 3;
    const int wn      = warp >> 2;

    auto issue_stage = [&](int s) {
        const int seg = s / KSTEPS;
        const int k0  = (s % KSTEPS) * BK;
        const __nv_bfloat16* Aseg = (seg == 2) ? Alo : Ahi;
        const __nv_bfloat16* Bseg = (seg == 1) ? Blo : Bhi;
        char* sA = smem + (s & 1) * STAGE;
        char* sB = sA + 16384;
#pragma unroll
        for (int j = 0; j < 4; ++j) {
            int c   = tid * 4 + j;
            int row = c >> 3, ch = c & 7;
            int grow = block_m + row;
            if (grow >= M) grow = M - 1;
            const char* src = reinterpret_cast<const char*>(Aseg + (size_t)grow * K + k0) + ch * 16;
            uint32_t dst = smem_u32(sA + row * 128 + ((ch ^ (row & 7)) << 4));
            CP_ASYNC16(dst, src);
        }
#pragma unroll
        for (int j = 0; j < 4; ++j) {
            int c   = tid * 4 + j;
            int row = c >> 3, ch = c & 7;
            const char* src = reinterpret_cast<const char*>(Bseg + (size_t)row * K + k0) + ch * 16;
            uint32_t dst = smem_u32(sB + row * 128 + ((ch ^ (row & 7)) << 4));
            CP_ASYNC16(dst, src);
        }
        CP_COMMIT();
    };

    float d[2][8][4];
#pragma unroll
    for (int i = 0; i < 2; ++i)
#pragma unroll
        for (int j = 0; j < 8; ++j)
#pragma unroll
            for (int q = 0; q < 4; ++q) d[i][j][q] = 0.f;

    issue_stage(0);

    for (int s = 0; s < NS; ++s) {
        if (s + 1 < NS) {
            issue_stage(s + 1);
            CP_WAIT(1);
        } else {
            CP_WAIT(0);
        }
        __syncthreads();

        const uint32_t sA = smem_u32(smem + (s & 1) * STAGE);
        const uint32_t sB = sA + 16384;

#pragma unroll
        for (int kk = 0; kk < 4; ++kk) {
            uint32_t a[2][4];
#pragma unroll
            for (int mt = 0; mt < 2; ++mt) {
                int row = wm * 32 + mt * 16 + (lane & 15);
                int ch  = kk * 2 + (lane >> 4);
                uint32_t addr = sA + row * 128 + ((ch ^ (row & 7)) << 4);
                LDSM4(a[mt][0], a[mt][1], a[mt][2], a[mt][3], addr);
            }
            uint32_t b[4][4];
#pragma unroll
            for (int nt2 = 0; nt2 < 4; ++nt2) {
                int row = wn * 64 + nt2 * 16 + (lane & 15);
                int ch  = kk * 2 + (lane >> 4);
                uint32_t addr = sB + row * 128 + ((ch ^ (row & 7)) << 4);
                LDSM4(b[nt2][0], b[nt2][1], b[nt2][2], b[nt2][3], addr);
            }
#pragma unroll
            for (int mt = 0; mt < 2; ++mt)
#pragma unroll
                for (int nt = 0; nt < 8; ++nt) {
                    int nt2 = nt >> 1, o = nt & 1;
                    MMA16816(d[mt][nt], a[mt], b[nt2][o], b[nt2][o + 2]);
                }
        }
        __syncthreads();
    }

    // ---- epilogue ----
    const int r0base = block_m + wm * 32 + (lane >> 2);
    const int cbase  = wn * 64 + (lane & 3) * 2;
#pragma unroll
    for (int mt = 0; mt < 2; ++mt) {
#pragma unroll
        for (int nt = 0; nt < 8; ++nt) {
            int c = cbase + nt * 8;
            float b0 = __ldg(bias + c);
            float b1 = __ldg(bias + c + 1);
#pragma unroll
            for (int half = 0; half < 2; ++half) {
                int row = r0base + mt * 16 + half * 8;
                if (row >= M) continue;
                float o0 = d[mt][nt][half * 2 + 0] + b0;
                float o1 = d[mt][nt][half * 2 + 1] + b1;
                if (LAYER1) {
                    o0 = fmaxf(o0, 0.f);
                    o1 = fmaxf(o1, 0.f);
                    // fp16 h for layer-2 gather
                    *reinterpret_cast<__half2*>(outH + (size_t)row * 128 + c) =
                        __floats2half2_rn(o0, o1);
                    // exact bf16 hi/lo root half of A2
                    __nv_bfloat16 h0, l0, h1, l1;
                    split_bf16(o0, h0, l0);
                    split_bf16(o1, h1, l1);
                    size_t ab = (size_t)row * 256 + 128 + c;
                    __nv_bfloat162 v;
                    v.x = h0; v.y = h1;
                    *reinterpret_cast<__nv_bfloat162*>(a2hi + ab) = v;
                    v.x = l0; v.y = l1;
                    *reinterpret_cast<__nv_bfloat162*>(a2lo + ab) = v;
                } else {
                    *reinterpret_cast<float2*>(outF + (size_t)row * 128 + c) =
                        make_float2(o0, o1);
                }
            }
        }
    }
}

// ---------------------------------------------------------------------------
extern "C" void kernel_launch(void* const* d_in, const int* in_sizes, int n_in,
                              void* d_out, int out_size) {
    const float* x   = (const float*)d_in[0];
    const int*   ei  = (const int*)  d_in[1];
    const float* Wl1 = (const float*)d_in[2];
    const float* bl1 = (const float*)d_in[3];
    const float* Wr1 = (const float*)d_in[4];
    const float* Wl2 = (const float*)d_in[5];
    const float* bl2 = (const float*)d_in[6];
    const float* Wr2 = (const float*)d_in[7];
    float* out = (float*)d_out;

    const int E = in_sizes[1] / 2;
    const int M = N_NODES;

    __nv_bfloat16 *a1hi, *a1lo, *a2hi, *a2lo, *b1hi, *b1lo, *b2hi, *b2lo;
    __half* hf;
    cudaGetSymbolAddress((void**)&a1hi, g_A1hi);
    cudaGetSymbolAddress((void**)&a1lo, g_A1lo);
    cudaGetSymbolAddress((void**)&a2hi, g_A2hi);
    cudaGetSymbolAddress((void**)&a2lo, g_A2lo);
    cudaGetSymbolAddress((void**)&b1hi, g_B1hi);
    cudaGetSymbolAddress((void**)&b1lo, g_B1lo);
    cudaGetSymbolAddress((void**)&b2hi, g_B2hi);
    cudaGetSymbolAddress((void**)&b2lo, g_B2lo);
    cudaGetSymbolAddress((void**)&hf,   g_hf);

    static bool attr_done = false;
    if (!attr_done) {
        cudaFuncSetAttribute(sage_gemm_mma<128, true>,
                             cudaFuncAttributeMaxDynamicSharedMemorySize, 65536);
        cudaFuncSetAttribute(sage_gemm_mma<256, false>,
                             cudaFuncAttributeMaxDynamicSharedMemorySize, 65536);
        attr_done = true;
    }

    const int gemm_blocks = (M + 127) / 128;

    // CSR build
    zero_deg<<<(N_NODES + 255) / 256, 256>>>();
    hist<<<(E + 255) / 256, 256>>>(ei, E);
    scan1<<<NB, SCAN_BLK>>>();
    scan2<<<1, 256>>>();
    scan3<<<(N_NODES + 255) / 256, 256>>>(E);
    fill<<<(E + 255) / 256, 256>>>(ei, E);

    // operand prep
    wconv<<<(128 * 128 + 128 * 256 + 255) / 256, 256>>>(Wl1, Wr1, Wl2, Wr2);
    convert_x<<<((long)M * 16 + 255) / 256, 256>>>(
        reinterpret_cast<const float4*>(x));

    // layer 1
    gather_mean<16, 128><<<((long)M * 16 + 255) / 256, 256>>>(
        reinterpret_cast<const float4*>(x), a1hi, a1lo);
    sage_gemm_mma<128, true><<<gemm_blocks, 256, 65536>>>(
        a1hi, a1lo, b1hi, b1lo, bl1, nullptr, hf, a2hi, a2lo, M);

    // layer 2
    gather_mean_h<<<((long)M * 16 + 255) / 256, 256>>>(
        reinterpret_cast<const uint4*>(hf), a2hi, a2lo);
    sage_gemm_mma<256, false><<<gemm_blocks, 256, 65536>>>(
        a2hi, a2lo, b2hi, b2lo, bl2, out, nullptr, nullptr, nullptr, M);
}

// round 7
// speedup vs baseline: 2.7631x; 1.0311x over previous
#include <cuda_runtime.h>
#include <cuda_bf16.h>
#include <cuda_fp16.h>
#include <cstdint>

#define N_NODES 100000
#define F_IN    64
#define HID     128
#define E_MAX   1700000
#define SCAN_BLK 512
#define NB ((N_NODES + SCAN_BLK - 1) / SCAN_BLK)   // 196

// ---------------------------------------------------------------------------
// Scratch (device globals — no runtime allocation)
// ---------------------------------------------------------------------------
__device__ __align__(16) __nv_bfloat16 g_A1hi[N_NODES * 128];  // [mean_x | x] hi
__device__ __align__(16) __nv_bfloat16 g_A1lo[N_NODES * 128];
__device__ __align__(16) __nv_bfloat16 g_A2hi[N_NODES * 256];  // [mean_h | h] hi
__device__ __align__(16) __nv_bfloat16 g_A2lo[N_NODES * 256];
__device__ __align__(16) __half g_xf[N_NODES * F_IN];          // x in fp16
__device__ __align__(16) __half g_hf[N_NODES * HID];           // layer-1 out fp16
__device__ __align__(16) __nv_bfloat16 g_B1hi[128 * 128];      // [Wl1 | Wr1] rows n, k-contig
__device__ __align__(16) __nv_bfloat16 g_B1lo[128 * 128];
__device__ __align__(16) __nv_bfloat16 g_B2hi[128 * 256];
__device__ __align__(16) __nv_bfloat16 g_B2lo[128 * 256];
__device__ int g_deg [N_NODES];
__device__ int g_off [N_NODES + 1];
__device__ int g_cur [N_NODES];
__device__ int g_bsum[NB];
__device__ int g_bbase[NB];
__device__ int g_csr [E_MAX];

// ---------------------------------------------------------------------------
__device__ __forceinline__ uint32_t smem_u32(const void* p) {
    return (uint32_t)__cvta_generic_to_shared(p);
}

#define CP_ASYNC16(dst, src) \
    asm volatile("cp.async.cg.shared.global [%0], [%1], 16;" :: "r"(dst), "l"(src))
#define CP_COMMIT() asm volatile("cp.async.commit_group;" ::: "memory")
#define CP_WAIT(n)  asm volatile("cp.async.wait_group %0;" :: "n"(n) : "memory")

#define LDSM4(r0, r1, r2, r3, addr) \
    asm volatile("ldmatrix.sync.aligned.m8n8.x4.shared.b16 {%0,%1,%2,%3}, [%4];" \
                 : "=r"(r0), "=r"(r1), "=r"(r2), "=r"(r3) : "r"(addr))

#define MMA16816(d, a, b0, b1) \
    asm volatile("mma.sync.aligned.m16n8k16.row.col.f32.bf16.bf16.f32 " \
                 "{%0,%1,%2,%3}, {%4,%5,%6,%7}, {%8,%9}, {%0,%1,%2,%3};" \
                 : "+f"((d)[0]), "+f"((d)[1]), "+f"((d)[2]), "+f"((d)[3]) \
                 : "r"((a)[0]), "r"((a)[1]), "r"((a)[2]), "r"((a)[3]), \
                   "r"(b0), "r"(b1))

__device__ __forceinline__ void split_bf16(float v, __nv_bfloat16& hi, __nv_bfloat16& lo) {
    hi = __float2bfloat16(v);
    lo = __float2bfloat16(v - __bfloat162float(hi));
}

// ---------------------------------------------------------------------------
// CSR build
// ---------------------------------------------------------------------------
__global__ void zero_deg() {
    int i = blockIdx.x * blockDim.x + threadIdx.x;
    if (i < N_NODES) g_deg[i] = 0;
}
__global__ void hist(const int* __restrict__ ei, int E) {
    int e = blockIdx.x * blockDim.x + threadIdx.x;
    if (e < E) atomicAdd(&g_deg[__ldg(ei + E + e)], 1);
}
__global__ void scan1() {
    __shared__ int s[SCAN_BLK];
    int t = threadIdx.x, b = blockIdx.x;
    int i = b * SCAN_BLK + t;
    int v = (i < N_NODES) ? g_deg[i] : 0;
    s[t] = v;
    __syncthreads();
#pragma unroll
    for (int off = 1; off < SCAN_BLK; off <<= 1) {
        int add = (t >= off) ? s[t - off] : 0;
        __syncthreads();
        if (t >= off) s[t] += add;
        __syncthreads();
    }
    if (i < N_NODES) g_off[i] = s[t] - v;
    if (t == SCAN_BLK - 1) g_bsum[b] = s[t];
}
__global__ void scan2() {
    __shared__ int s[256];
    int t = threadIdx.x;
    int v = (t < NB) ? g_bsum[t] : 0;
    s[t] = v;
    __syncthreads();
#pragma unroll
    for (int off = 1; off < 256; off <<= 1) {
        int add = (t >= off) ? s[t - off] : 0;
        __syncthreads();
        if (t >= off) s[t] += add;
        __syncthreads();
    }
    if (t < NB) g_bbase[t] = s[t] - v;
}
__global__ void scan3(int E) {
    int i = blockIdx.x * blockDim.x + threadIdx.x;
    if (i < N_NODES) {
        int o = g_off[i] + g_bbase[i / SCAN_BLK];
        g_off[i] = o;
        g_cur[i] = o;
    }
    if (i == 0) g_off[N_NODES] = E;
}
__global__ void fill(const int* __restrict__ ei, int E) {
    int e = blockIdx.x * blockDim.x + threadIdx.x;
    if (e >= E) return;
    int src = __ldg(ei + e);
    int dst = __ldg(ei + E + e);
    int pos = atomicAdd(&g_cur[dst], 1);
    g_csr[pos] = src;
}

// ---------------------------------------------------------------------------
// Weight convert: fp32 [WL|WR] -> bf16 hi/lo, rows n, virtual-k contiguous
// ---------------------------------------------------------------------------
__global__ void wconv(const float* __restrict__ WL1, const float* __restrict__ WR1,
                      const float* __restrict__ WL2, const float* __restrict__ WR2) {
    int idx = blockIdx.x * blockDim.x + threadIdx.x;
    if (idx < 128 * 128) {                      // layer 1, K = 128
        int n = idx >> 7, k = idx & 127;
        float v = (k < 64) ? __ldg(WL1 + n * 64 + k) : __ldg(WR1 + n * 64 + (k - 64));
        __nv_bfloat16 hi, lo;
        split_bf16(v, hi, lo);
        g_B1hi[idx] = hi;
        g_B1lo[idx] = lo;
    } else if (idx < 128 * 128 + 128 * 256) {   // layer 2, K = 256
        int j = idx - 128 * 128;
        int n = j >> 8, k = j & 255;
        float v = (k < 128) ? __ldg(WL2 + n * 128 + k) : __ldg(WR2 + n * 128 + (k - 128));
        __nv_bfloat16 hi, lo;
        split_bf16(v, hi, lo);
        g_B2hi[j] = hi;
        g_B2lo[j] = lo;
    }
}

// ---------------------------------------------------------------------------
// x -> fp16 copy (for gather) + exact bf16 hi/lo root half (A1 cols 64..127)
// ---------------------------------------------------------------------------
__global__ void convert_x(const float4* __restrict__ x4) {
    int idx = blockIdx.x * blockDim.x + threadIdx.x;
    if (idx >= N_NODES * 16) return;
    int n = idx >> 4, q = idx & 15;
    float4 v = __ldg(x4 + idx);
    // fp16 side copy
    __half2* pf = reinterpret_cast<__half2*>(g_xf + (size_t)n * 64 + q * 4);
    pf[0] = __floats2half2_rn(v.x, v.y);
    pf[1] = __floats2half2_rn(v.z, v.w);
    // exact bf16 hi/lo root
    __nv_bfloat16 h0, l0, h1, l1, h2, l2, h3, l3;
    split_bf16(v.x, h0, l0); split_bf16(v.y, h1, l1);
    split_bf16(v.z, h2, l2); split_bf16(v.w, h3, l3);
    size_t base = (size_t)n * 128 + 64 + q * 4;
    __nv_bfloat162* ph = reinterpret_cast<__nv_bfloat162*>(g_A1hi + base);
    __nv_bfloat162* pl = reinterpret_cast<__nv_bfloat162*>(g_A1lo + base);
    __nv_bfloat162 a; a.x = h0; a.y = h1; ph[0] = a;
    a.x = h2; a.y = h3; ph[1] = a;
    a.x = l0; a.y = l1; pl[0] = a;
    a.x = l2; a.y = l3; pl[1] = a;
}

// ---------------------------------------------------------------------------
// fp16 gather-reduce (mean): FQ 16B-chunks (8 halfs) per node row.
//   FQ=8  -> 64-wide rows (x),  FQ=16 -> 128-wide rows (h)
//   Output: bf16 hi/lo at ahi/alo + n*AK + q*8  (mean half of A)
// ---------------------------------------------------------------------------
template <int FQ, int AK>
__global__ void gather_mean_f16(const uint4* __restrict__ srcH,
                                __nv_bfloat16* __restrict__ ahi,
                                __nv_bfloat16* __restrict__ alo) {
    int idx = blockIdx.x * blockDim.x + threadIdx.x;
    int n = idx / FQ;
    if (n >= N_NODES) return;
    int q = idx % FQ;
    int s  = g_off[n];
    int e2 = g_off[n + 1];

    float acc[8];
#pragma unroll
    for (int j = 0; j < 8; ++j) acc[j] = 0.f;

    auto accum = [&](uint4 v) {
        const __half2* p = reinterpret_cast<const __half2*>(&v);
#pragma unroll
        for (int w = 0; w < 4; ++w) {
            float2 f = __half22float2(p[w]);
            acc[2 * w + 0] += f.x;
            acc[2 * w + 1] += f.y;
        }
    };

    int i = s;
    for (; i + 4 <= e2; i += 4) {
        int s0 = g_csr[i], s1 = g_csr[i + 1], s2 = g_csr[i + 2], s3 = g_csr[i + 3];
        uint4 v0 = __ldg(srcH + (size_t)s0 * FQ + q);
        uint4 v1 = __ldg(srcH + (size_t)s1 * FQ + q);
        uint4 v2 = __ldg(srcH + (size_t)s2 * FQ + q);
        uint4 v3 = __ldg(srcH + (size_t)s3 * FQ + q);
        accum(v0); accum(v1); accum(v2); accum(v3);
    }
    for (; i < e2; ++i)
        accum(__ldg(srcH + (size_t)g_csr[i] * FQ + q));

    float inv = 1.0f / fmaxf((float)(e2 - s), 1.0f);

    __nv_bfloat16 hb[8], lb[8];
#pragma unroll
    for (int j = 0; j < 8; ++j) {
        float m = acc[j] * inv;
        split_bf16(m, hb[j], lb[j]);
    }
    size_t base = (size_t)n * AK + q * 8;
    uint4 vh, vl;
    __nv_bfloat162* ph = reinterpret_cast<__nv_bfloat162*>(&vh);
    __nv_bfloat162* pl = reinterpret_cast<__nv_bfloat162*>(&vl);
#pragma unroll
    for (int w = 0; w < 4; ++w) {
        __nv_bfloat162 t;
        t.x = hb[2 * w]; t.y = hb[2 * w + 1]; ph[w] = t;
        t.x = lb[2 * w]; t.y = lb[2 * w + 1]; pl[w] = t;
    }
    *reinterpret_cast<uint4*>(ahi + base) = vh;
    *reinterpret_cast<uint4*>(alo + base) = vl;
}

// ---------------------------------------------------------------------------
// mma.sync bf16 hi/lo-compensated SAGE GEMM.
//   BM=128 BN=128 BK=64, 8 warps (4m x 2n), warp tile 32x64.
//   Virtual K loop = 3 segments: Ahi*Bhi, Ahi*Blo, Alo*Bhi.
//   cp.async double-buffered smem, XOR-swizzled 16B chunks for ldmatrix.
// LAYER1: writes h fp16 AND bf16 hi/lo root half into A2 cols 128..255.
// ---------------------------------------------------------------------------
template <int K, bool LAYER1>
__global__ void __launch_bounds__(256)
sage_gemm_mma(const __nv_bfloat16* __restrict__ Ahi,
              const __nv_bfloat16* __restrict__ Alo,
              const __nv_bfloat16* __restrict__ Bhi,
              const __nv_bfloat16* __restrict__ Blo,
              const float* __restrict__ bias,
              float* __restrict__ outF,
              __half* __restrict__ outH,
              __nv_bfloat16* __restrict__ a2hi,
              __nv_bfloat16* __restrict__ a2lo,
              int M) {
    constexpr int BK     = 64;
    constexpr int KSTEPS = K / BK;
    constexpr int NS     = 3 * KSTEPS;
    constexpr int STAGE  = 32768;          // A 16KB + B 16KB

    extern __shared__ char smem[];

    const int tid     = threadIdx.x;
    const int block_m = blockIdx.x * 128;
    const int warp    = tid >> 5;
    const int lane    = tid & 31;
    const int wm      = warp & 3;
    const int wn      = warp >> 2;

    auto issue_stage = [&](int s) {
        const int seg = s / KSTEPS;
        const int k0  = (s % KSTEPS) * BK;
        const __nv_bfloat16* Aseg = (seg == 2) ? Alo : Ahi;
        const __nv_bfloat16* Bseg = (seg == 1) ? Blo : Bhi;
        char* sA = smem + (s & 1) * STAGE;
        char* sB = sA + 16384;
#pragma unroll
        for (int j = 0; j < 4; ++j) {
            int c   = tid * 4 + j;
            int row = c >> 3, ch = c & 7;
            int grow = block_m + row;
            if (grow >= M) grow = M - 1;
            const char* src = reinterpret_cast<const char*>(Aseg + (size_t)grow * K + k0) + ch * 16;
            uint32_t dst = smem_u32(sA + row * 128 + ((ch ^ (row & 7)) << 4));
            CP_ASYNC16(dst, src);
        }
#pragma unroll
        for (int j = 0; j < 4; ++j) {
            int c   = tid * 4 + j;
            int row = c >> 3, ch = c & 7;
            const char* src = reinterpret_cast<const char*>(Bseg + (size_t)row * K + k0) + ch * 16;
            uint32_t dst = smem_u32(sB + row * 128 + ((ch ^ (row & 7)) << 4));
            CP_ASYNC16(dst, src);
        }
        CP_COMMIT();
    };

    float d[2][8][4];
#pragma unroll
    for (int i = 0; i < 2; ++i)
#pragma unroll
        for (int j = 0; j < 8; ++j)
#pragma unroll
            for (int q = 0; q < 4; ++q) d[i][j][q] = 0.f;

    issue_stage(0);

    for (int s = 0; s < NS; ++s) {
        if (s + 1 < NS) {
            issue_stage(s + 1);
            CP_WAIT(1);
        } else {
            CP_WAIT(0);
        }
        __syncthreads();

        const uint32_t sA = smem_u32(smem + (s & 1) * STAGE);
        const uint32_t sB = sA + 16384;

#pragma unroll
        for (int kk = 0; kk < 4; ++kk) {
            uint32_t a[2][4];
#pragma unroll
            for (int mt = 0; mt < 2; ++mt) {
                int row = wm * 32 + mt * 16 + (lane & 15);
                int ch  = kk * 2 + (lane >> 4);
                uint32_t addr = sA + row * 128 + ((ch ^ (row & 7)) << 4);
                LDSM4(a[mt][0], a[mt][1], a[mt][2], a[mt][3], addr);
            }
            uint32_t b[4][4];
#pragma unroll
            for (int nt2 = 0; nt2 < 4; ++nt2) {
                int row = wn * 64 + nt2 * 16 + (lane & 15);
                int ch  = kk * 2 + (lane >> 4);
                uint32_t addr = sB + row * 128 + ((ch ^ (row & 7)) << 4);
                LDSM4(b[nt2][0], b[nt2][1], b[nt2][2], b[nt2][3], addr);
            }
#pragma unroll
            for (int mt = 0; mt < 2; ++mt)
#pragma unroll
                for (int nt = 0; nt < 8; ++nt) {
                    int nt2 = nt >> 1, o = nt & 1;
                    MMA16816(d[mt][nt], a[mt], b[nt2][o], b[nt2][o + 2]);
                }
        }
        __syncthreads();
    }

    // ---- epilogue ----
    const int r0base = block_m + wm * 32 + (lane >> 2);
    const int cbase  = wn * 64 + (lane & 3) * 2;
#pragma unroll
    for (int mt = 0; mt < 2; ++mt) {
#pragma unroll
        for (int nt = 0; nt < 8; ++nt) {
            int c = cbase + nt * 8;
            float b0 = __ldg(bias + c);
            float b1 = __ldg(bias + c + 1);
#pragma unroll
            for (int half = 0; half < 2; ++half) {
                int row = r0base + mt * 16 + half * 8;
                if (row >= M) continue;
                float o0 = d[mt][nt][half * 2 + 0] + b0;
                float o1 = d[mt][nt][half * 2 + 1] + b1;
                if (LAYER1) {
                    o0 = fmaxf(o0, 0.f);
                    o1 = fmaxf(o1, 0.f);
                    // fp16 h for layer-2 gather
                    *reinterpret_cast<__half2*>(outH + (size_t)row * 128 + c) =
                        __floats2half2_rn(o0, o1);
                    // exact bf16 hi/lo root half of A2
                    __nv_bfloat16 h0, l0, h1, l1;
                    split_bf16(o0, h0, l0);
                    split_bf16(o1, h1, l1);
                    size_t ab = (size_t)row * 256 + 128 + c;
                    __nv_bfloat162 v;
                    v.x = h0; v.y = h1;
                    *reinterpret_cast<__nv_bfloat162*>(a2hi + ab) = v;
                    v.x = l0; v.y = l1;
                    *reinterpret_cast<__nv_bfloat162*>(a2lo + ab) = v;
                } else {
                    *reinterpret_cast<float2*>(outF + (size_t)row * 128 + c) =
                        make_float2(o0, o1);
                }
            }
        }
    }
}

// ---------------------------------------------------------------------------
extern "C" void kernel_launch(void* const* d_in, const int* in_sizes, int n_in,
                              void* d_out, int out_size) {
    const float* x   = (const float*)d_in[0];
    const int*   ei  = (const int*)  d_in[1];
    const float* Wl1 = (const float*)d_in[2];
    const float* bl1 = (const float*)d_in[3];
    const float* Wr1 = (const float*)d_in[4];
    const float* Wl2 = (const float*)d_in[5];
    const float* bl2 = (const float*)d_in[6];
    const float* Wr2 = (const float*)d_in[7];
    float* out = (float*)d_out;

    const int E = in_sizes[1] / 2;
    const int M = N_NODES;

    __nv_bfloat16 *a1hi, *a1lo, *a2hi, *a2lo, *b1hi, *b1lo, *b2hi, *b2lo;
    __half *hf, *xf;
    cudaGetSymbolAddress((void**)&a1hi, g_A1hi);
    cudaGetSymbolAddress((void**)&a1lo, g_A1lo);
    cudaGetSymbolAddress((void**)&a2hi, g_A2hi);
    cudaGetSymbolAddress((void**)&a2lo, g_A2lo);
    cudaGetSymbolAddress((void**)&b1hi, g_B1hi);
    cudaGetSymbolAddress((void**)&b1lo, g_B1lo);
    cudaGetSymbolAddress((void**)&b2hi, g_B2hi);
    cudaGetSymbolAddress((void**)&b2lo, g_B2lo);
    cudaGetSymbolAddress((void**)&hf,   g_hf);
    cudaGetSymbolAddress((void**)&xf,   g_xf);

    static bool attr_done = false;
    if (!attr_done) {
        cudaFuncSetAttribute(sage_gemm_mma<128, true>,
                             cudaFuncAttributeMaxDynamicSharedMemorySize, 65536);
        cudaFuncSetAttribute(sage_gemm_mma<256, false>,
                             cudaFuncAttributeMaxDynamicSharedMemorySize, 65536);
        attr_done = true;
    }

    const int gemm_blocks = (M + 127) / 128;

    // CSR build
    zero_deg<<<(N_NODES + 255) / 256, 256>>>();
    hist<<<(E + 255) / 256, 256>>>(ei, E);
    scan1<<<NB, SCAN_BLK>>>();
    scan2<<<1, 256>>>();
    scan3<<<(N_NODES + 255) / 256, 256>>>(E);
    fill<<<(E + 255) / 256, 256>>>(ei, E);

    // operand prep
    wconv<<<(128 * 128 + 128 * 256 + 255) / 256, 256>>>(Wl1, Wr1, Wl2, Wr2);
    convert_x<<<((long)M * 16 + 255) / 256, 256>>>(
        reinterpret_cast<const float4*>(x));

    // layer 1
    gather_mean_f16<8, 128><<<((long)M * 8 + 255) / 256, 256>>>(
        reinterpret_cast<const uint4*>(xf), a1hi, a1lo);
    sage_gemm_mma<128, true><<<gemm_blocks, 256, 65536>>>(
        a1hi, a1lo, b1hi, b1lo, bl1, nullptr, hf, a2hi, a2lo, M);

    // layer 2
    gather_mean_f16<16, 256><<<((long)M * 16 + 255) / 256, 256>>>(
        reinterpret_cast<const uint4*>(hf), a2hi, a2lo);
    sage_gemm_mma<256, false><<<gemm_blocks, 256, 65536>>>(
        a2hi, a2lo, b2hi, b2lo, bl2, out, nullptr, nullptr, nullptr, M);
}

// round 8
// speedup vs baseline: 3.2412x; 1.1730x over previous
#include <cuda_runtime.h>
#include <cuda_bf16.h>
#include <cuda_fp16.h>
#include <cstdint>

#define N_NODES 100000
#define F_IN    64
#define HID     128
#define E_MAX   1700000
#define SCAN_BLK 512
#define NB ((N_NODES + SCAN_BLK - 1) / SCAN_BLK)   // 196

// ---------------------------------------------------------------------------
// Scratch (device globals — no runtime allocation)
// ---------------------------------------------------------------------------
__device__ __align__(16) __half g_xf[N_NODES * F_IN];          // x fp16
__device__ __align__(16) __half g_m1[N_NODES * F_IN];          // mean(x) fp16
__device__ __align__(16) __half g_hf[N_NODES * HID];           // h fp16
__device__ __align__(16) __half g_m2[N_NODES * HID];           // mean(h) fp16
__device__ __align__(16) __nv_bfloat16 g_B1hi[128 * 128];      // [Wl1|Wr1] rows n, k-contig
__device__ __align__(16) __nv_bfloat16 g_B1lo[128 * 128];
__device__ __align__(16) __nv_bfloat16 g_B2hi[128 * 256];
__device__ __align__(16) __nv_bfloat16 g_B2lo[128 * 256];
__device__ int g_deg [N_NODES];
__device__ int g_off [N_NODES + 1];
__device__ int g_cur [N_NODES];
__device__ int g_bsum[NB];
__device__ int g_bbase[NB];
__device__ int g_csr [E_MAX];

// ---------------------------------------------------------------------------
__device__ __forceinline__ uint32_t smem_u32(const void* p) {
    return (uint32_t)__cvta_generic_to_shared(p);
}

#define CP_ASYNC16(dst, src) \
    asm volatile("cp.async.cg.shared.global [%0], [%1], 16;" :: "r"(dst), "l"(src))
#define CP_COMMIT() asm volatile("cp.async.commit_group;" ::: "memory")
#define CP_WAIT(n)  asm volatile("cp.async.wait_group %0;" :: "n"(n) : "memory")

#define LDSM4(r0, r1, r2, r3, addr) \
    asm volatile("ldmatrix.sync.aligned.m8n8.x4.shared.b16 {%0,%1,%2,%3}, [%4];" \
                 : "=r"(r0), "=r"(r1), "=r"(r2), "=r"(r3) : "r"(addr))

#define MMA16816(d, a, b0, b1) \
    asm volatile("mma.sync.aligned.m16n8k16.row.col.f32.bf16.bf16.f32 " \
                 "{%0,%1,%2,%3}, {%4,%5,%6,%7}, {%8,%9}, {%0,%1,%2,%3};" \
                 : "+f"((d)[0]), "+f"((d)[1]), "+f"((d)[2]), "+f"((d)[3]) \
                 : "r"((a)[0]), "r"((a)[1]), "r"((a)[2]), "r"((a)[3]), \
                   "r"(b0), "r"(b1))

__device__ __forceinline__ void split_bf16(float v, __nv_bfloat16& hi, __nv_bfloat16& lo) {
    hi = __float2bfloat16(v);
    lo = __float2bfloat16(v - __bfloat162float(hi));
}

// ---------------------------------------------------------------------------
// CSR build
// ---------------------------------------------------------------------------
__global__ void zero_deg() {
    int i = blockIdx.x * blockDim.x + threadIdx.x;
    if (i < N_NODES) g_deg[i] = 0;
}
__global__ void hist(const int* __restrict__ ei, int E) {
    int e = blockIdx.x * blockDim.x + threadIdx.x;
    if (e < E) atomicAdd(&g_deg[__ldg(ei + E + e)], 1);
}
__global__ void scan1() {
    __shared__ int s[SCAN_BLK];
    int t = threadIdx.x, b = blockIdx.x;
    int i = b * SCAN_BLK + t;
    int v = (i < N_NODES) ? g_deg[i] : 0;
    s[t] = v;
    __syncthreads();
#pragma unroll
    for (int off = 1; off < SCAN_BLK; off <<= 1) {
        int add = (t >= off) ? s[t - off] : 0;
        __syncthreads();
        if (t >= off) s[t] += add;
        __syncthreads();
    }
    if (i < N_NODES) g_off[i] = s[t] - v;
    if (t == SCAN_BLK - 1) g_bsum[b] = s[t];
}
__global__ void scan2() {
    __shared__ int s[256];
    int t = threadIdx.x;
    int v = (t < NB) ? g_bsum[t] : 0;
    s[t] = v;
    __syncthreads();
#pragma unroll
    for (int off = 1; off < 256; off <<= 1) {
        int add = (t >= off) ? s[t - off] : 0;
        __syncthreads();
        if (t >= off) s[t] += add;
        __syncthreads();
    }
    if (t < NB) g_bbase[t] = s[t] - v;
}
__global__ void scan3(int E) {
    int i = blockIdx.x * blockDim.x + threadIdx.x;
    if (i < N_NODES) {
        int o = g_off[i] + g_bbase[i / SCAN_BLK];
        g_off[i] = o;
        g_cur[i] = o;
    }
    if (i == 0) g_off[N_NODES] = E;
}
__global__ void fill(const int* __restrict__ ei, int E) {
    int e = blockIdx.x * blockDim.x + threadIdx.x;
    if (e >= E) return;
    int src = __ldg(ei + e);
    int dst = __ldg(ei + E + e);
    int pos = atomicAdd(&g_cur[dst], 1);
    g_csr[pos] = src;
}

// ---------------------------------------------------------------------------
// Weight convert: fp32 [WL|WR] -> bf16 hi/lo, rows n, virtual-k contiguous
// ---------------------------------------------------------------------------
__global__ void wconv(const float* __restrict__ WL1, const float* __restrict__ WR1,
                      const float* __restrict__ WL2, const float* __restrict__ WR2) {
    int idx = blockIdx.x * blockDim.x + threadIdx.x;
    if (idx < 128 * 128) {                      // layer 1, K = 128
        int n = idx >> 7, k = idx & 127;
        float v = (k < 64) ? __ldg(WL1 + n * 64 + k) : __ldg(WR1 + n * 64 + (k - 64));
        __nv_bfloat16 hi, lo;
        split_bf16(v, hi, lo);
        g_B1hi[idx] = hi;
        g_B1lo[idx] = lo;
    } else if (idx < 128 * 128 + 128 * 256) {   // layer 2, K = 256
        int j = idx - 128 * 128;
        int n = j >> 8, k = j & 255;
        float v = (k < 128) ? __ldg(WL2 + n * 128 + k) : __ldg(WR2 + n * 128 + (k - 128));
        __nv_bfloat16 hi, lo;
        split_bf16(v, hi, lo);
        g_B2hi[j] = hi;
        g_B2lo[j] = lo;
    }
}

// ---------------------------------------------------------------------------
// x fp32 -> fp16 cast (8 halfs per thread)
// ---------------------------------------------------------------------------
__global__ void convert_x(const float4* __restrict__ x4, __half* __restrict__ xf) {
    int idx = blockIdx.x * blockDim.x + threadIdx.x;
    if (idx >= N_NODES * 8) return;
    float4 v0 = __ldg(x4 + idx * 2);
    float4 v1 = __ldg(x4 + idx * 2 + 1);
    uint4 o;
    __half2* p = reinterpret_cast<__half2*>(&o);
    p[0] = __floats2half2_rn(v0.x, v0.y);
    p[1] = __floats2half2_rn(v0.z, v0.w);
    p[2] = __floats2half2_rn(v1.x, v1.y);
    p[3] = __floats2half2_rn(v1.z, v1.w);
    *reinterpret_cast<uint4*>(xf + (size_t)idx * 8) = o;
}

// ---------------------------------------------------------------------------
// fp16 gather-reduce (mean): FQ 16B-chunks (8 halfs) per node row -> fp16 mean
// ---------------------------------------------------------------------------
template <int FQ>
__global__ void gather_mean_f16(const uint4* __restrict__ srcH,
                                __half* __restrict__ outm) {
    int idx = blockIdx.x * blockDim.x + threadIdx.x;
    int n = idx / FQ;
    if (n >= N_NODES) return;
    int q = idx % FQ;
    int s  = g_off[n];
    int e2 = g_off[n + 1];

    float acc[8];
#pragma unroll
    for (int j = 0; j < 8; ++j) acc[j] = 0.f;

    auto accum = [&](uint4 v) {
        const __half2* p = reinterpret_cast<const __half2*>(&v);
#pragma unroll
        for (int w = 0; w < 4; ++w) {
            float2 f = __half22float2(p[w]);
            acc[2 * w + 0] += f.x;
            acc[2 * w + 1] += f.y;
        }
    };

    int i = s;
    for (; i + 4 <= e2; i += 4) {
        int s0 = g_csr[i], s1 = g_csr[i + 1], s2 = g_csr[i + 2], s3 = g_csr[i + 3];
        uint4 v0 = __ldg(srcH + (size_t)s0 * FQ + q);
        uint4 v1 = __ldg(srcH + (size_t)s1 * FQ + q);
        uint4 v2 = __ldg(srcH + (size_t)s2 * FQ + q);
        uint4 v3 = __ldg(srcH + (size_t)s3 * FQ + q);
        accum(v0); accum(v1); accum(v2); accum(v3);
    }
    for (; i < e2; ++i)
        accum(__ldg(srcH + (size_t)g_csr[i] * FQ + q));

    float inv = 1.0f / fmaxf((float)(e2 - s), 1.0f);

    uint4 o;
    __half2* p = reinterpret_cast<__half2*>(&o);
#pragma unroll
    for (int w = 0; w < 4; ++w)
        p[w] = __floats2half2_rn(acc[2 * w] * inv, acc[2 * w + 1] * inv);
    *reinterpret_cast<uint4*>(outm + ((size_t)n * FQ + q) * 8) = o;
}

// ---------------------------------------------------------------------------
// mma.sync SAGE GEMM, fp16 A with in-kernel bf16 hi/lo split.
//   A (virtual) = [mean fp16 | root fp16], width K halfs; row stride K bytes each half-buffer.
//   Per k-stage: global->reg A fp16, split -> sAhi/sAlo smem;
//   cp.async double-buffered Bhi/Blo tiles; 3 compensation products per kk:
//     D += Ahi*Bhi + Alo*Bhi + Ahi*Blo
//   smem: sAhi 16K | sAlo 16K | B[2] x (Bhi 16K | Blo 16K)  = 96KB
// ---------------------------------------------------------------------------
template <int K, bool LAYER1>
__global__ void __launch_bounds__(256)
sage_gemm_mma(const __half* __restrict__ Am,
              const __half* __restrict__ Ar,
              const __nv_bfloat16* __restrict__ Bhi,
              const __nv_bfloat16* __restrict__ Blo,
              const float* __restrict__ bias,
              float* __restrict__ outF,
              __half* __restrict__ outH,
              int M) {
    constexpr int BK = 64;
    constexpr int NT = K / BK;
    constexpr int KH = K / 2;

    extern __shared__ char smem[];
    const uint32_t sbase = smem_u32(smem);
    const uint32_t sAhi  = sbase;
    const uint32_t sAlo  = sbase + 16384;

    const int tid     = threadIdx.x;
    const int block_m = blockIdx.x * 128;
    const int warp    = tid >> 5;
    const int lane    = tid & 31;
    const int wm      = warp & 3;
    const int wn      = warp >> 2;

    uint4 areg[4];

    auto load_a = [&](int kt) {
        const bool mean = (kt * BK) < KH;
        const __half* src = mean ? Am : Ar;
        const int colb = mean ? kt * BK : kt * BK - KH;
#pragma unroll
        for (int j = 0; j < 4; ++j) {
            int c = j * 256 + tid;
            int row = c >> 3, ch = c & 7;
            int grow = block_m + row;
            if (grow >= M) grow = M - 1;
            areg[j] = __ldg(reinterpret_cast<const uint4*>(
                reinterpret_cast<const char*>(src) +
                (size_t)grow * (2 * KH) + colb * 2 + ch * 16));
        }
    };

    auto store_a = [&]() {
#pragma unroll
        for (int j = 0; j < 4; ++j) {
            int c = j * 256 + tid;
            int row = c >> 3, ch = c & 7;
            uint4 vh, vl;
            const __half2* p = reinterpret_cast<const __half2*>(&areg[j]);
            uint32_t* wh = reinterpret_cast<uint32_t*>(&vh);
            uint32_t* wl = reinterpret_cast<uint32_t*>(&vl);
#pragma unroll
            for (int w = 0; w < 4; ++w) {
                float2 f = __half22float2(p[w]);
                __nv_bfloat16 h0, l0, h1, l1;
                split_bf16(f.x, h0, l0);
                split_bf16(f.y, h1, l1);
                __nv_bfloat162 th; th.x = h0; th.y = h1;
                __nv_bfloat162 tl; tl.x = l0; tl.y = l1;
                wh[w] = *reinterpret_cast<uint32_t*>(&th);
                wl[w] = *reinterpret_cast<uint32_t*>(&tl);
            }
            int off = row * 128 + ((ch ^ (row & 7)) << 4);
            *reinterpret_cast<uint4*>(smem + off) = vh;
            *reinterpret_cast<uint4*>(smem + 16384 + off) = vl;
        }
    };

    auto issue_b = [&](int kt) {
        char* dst = smem + 32768 + (kt & 1) * 32768;
#pragma unroll
        for (int j = 0; j < 4; ++j) {
            int c = j * 256 + tid;
            int n = c >> 3, ch = c & 7;
            int off = n * 128 + ((ch ^ (n & 7)) << 4);
            const char* sh = reinterpret_cast<const char*>(Bhi) +
                             (size_t)n * 2 * K + kt * 128 + ch * 16;
            CP_ASYNC16(smem_u32(dst + off), sh);
            const char* sl = reinterpret_cast<const char*>(Blo) +
                             (size_t)n * 2 * K + kt * 128 + ch * 16;
            CP_ASYNC16(smem_u32(dst + 16384 + off), sl);
        }
        CP_COMMIT();
    };

    float d[2][8][4];
#pragma unroll
    for (int i = 0; i < 2; ++i)
#pragma unroll
        for (int j = 0; j < 8; ++j)
#pragma unroll
            for (int q = 0; q < 4; ++q) d[i][j][q] = 0.f;

    load_a(0);
    issue_b(0);

    for (int kt = 0; kt < NT; ++kt) {
        store_a();                       // A smem protected by prev trailing sync
        if (kt + 1 < NT) {
            load_a(kt + 1);
            issue_b(kt + 1);
            CP_WAIT(1);                  // B(kt) ready
        } else {
            CP_WAIT(0);
        }
        __syncthreads();

        const uint32_t sBh = sbase + 32768 + (kt & 1) * 32768;
        const uint32_t sBl = sBh + 16384;

#pragma unroll
        for (int kk = 0; kk < 4; ++kk) {
            uint32_t ah[2][4], al[2][4];
#pragma unroll
            for (int mt = 0; mt < 2; ++mt) {
                int row = wm * 32 + mt * 16 + (lane & 15);
                int ch  = kk * 2 + (lane >> 4);
                int off = row * 128 + ((ch ^ (row & 7)) << 4);
                LDSM4(ah[mt][0], ah[mt][1], ah[mt][2], ah[mt][3], sAhi + off);
                LDSM4(al[mt][0], al[mt][1], al[mt][2], al[mt][3], sAlo + off);
            }
            uint32_t b[4][4];
#pragma unroll
            for (int nt2 = 0; nt2 < 4; ++nt2) {
                int row = wn * 64 + nt2 * 16 + (lane & 15);
                int ch  = kk * 2 + (lane >> 4);
                int off = row * 128 + ((ch ^ (row & 7)) << 4);
                LDSM4(b[nt2][0], b[nt2][1], b[nt2][2], b[nt2][3], sBh + off);
            }
#pragma unroll
            for (int mt = 0; mt < 2; ++mt)
#pragma unroll
                for (int nt = 0; nt < 8; ++nt) {
                    int nt2 = nt >> 1, o = nt & 1;
                    MMA16816(d[mt][nt], ah[mt], b[nt2][o], b[nt2][o + 2]);
                    MMA16816(d[mt][nt], al[mt], b[nt2][o], b[nt2][o + 2]);
                }
#pragma unroll
            for (int nt2 = 0; nt2 < 4; ++nt2) {
                int row = wn * 64 + nt2 * 16 + (lane & 15);
                int ch  = kk * 2 + (lane >> 4);
                int off = row * 128 + ((ch ^ (row & 7)) << 4);
                LDSM4(b[nt2][0], b[nt2][1], b[nt2][2], b[nt2][3], sBl + off);
            }
#pragma unroll
            for (int mt = 0; mt < 2; ++mt)
#pragma unroll
                for (int nt = 0; nt < 8; ++nt) {
                    int nt2 = nt >> 1, o = nt & 1;
                    MMA16816(d[mt][nt], ah[mt], b[nt2][o], b[nt2][o + 2]);
                }
        }
        __syncthreads();
    }

    // ---- epilogue ----
    const int r0base = block_m + wm * 32 + (lane >> 2);
    const int cbase  = wn * 64 + (lane & 3) * 2;
#pragma unroll
    for (int mt = 0; mt < 2; ++mt) {
#pragma unroll
        for (int nt = 0; nt < 8; ++nt) {
            int c = cbase + nt * 8;
            float b0 = __ldg(bias + c);
            float b1 = __ldg(bias + c + 1);
#pragma unroll
            for (int half = 0; half < 2; ++half) {
                int row = r0base + mt * 16 + half * 8;
                if (row >= M) continue;
                float o0 = d[mt][nt][half * 2 + 0] + b0;
                float o1 = d[mt][nt][half * 2 + 1] + b1;
                if (LAYER1) {
                    o0 = fmaxf(o0, 0.f);
                    o1 = fmaxf(o1, 0.f);
                    *reinterpret_cast<__half2*>(outH + (size_t)row * 128 + c) =
                        __floats2half2_rn(o0, o1);
                } else {
                    *reinterpret_cast<float2*>(outF + (size_t)row * 128 + c) =
                        make_float2(o0, o1);
                }
            }
        }
    }
}

// ---------------------------------------------------------------------------
extern "C" void kernel_launch(void* const* d_in, const int* in_sizes, int n_in,
                              void* d_out, int out_size) {
    const float* x   = (const float*)d_in[0];
    const int*   ei  = (const int*)  d_in[1];
    const float* Wl1 = (const float*)d_in[2];
    const float* bl1 = (const float*)d_in[3];
    const float* Wr1 = (const float*)d_in[4];
    const float* Wl2 = (const float*)d_in[5];
    const float* bl2 = (const float*)d_in[6];
    const float* Wr2 = (const float*)d_in[7];
    float* out = (float*)d_out;

    const int E = in_sizes[1] / 2;
    const int M = N_NODES;

    __nv_bfloat16 *b1hi, *b1lo, *b2hi, *b2lo;
    __half *xf, *m1, *hf, *m2;
    cudaGetSymbolAddress((void**)&b1hi, g_B1hi);
    cudaGetSymbolAddress((void**)&b1lo, g_B1lo);
    cudaGetSymbolAddress((void**)&b2hi, g_B2hi);
    cudaGetSymbolAddress((void**)&b2lo, g_B2lo);
    cudaGetSymbolAddress((void**)&xf,   g_xf);
    cudaGetSymbolAddress((void**)&m1,   g_m1);
    cudaGetSymbolAddress((void**)&hf,   g_hf);
    cudaGetSymbolAddress((void**)&m2,   g_m2);

    static bool attr_done = false;
    if (!attr_done) {
        cudaFuncSetAttribute(sage_gemm_mma<128, true>,
                             cudaFuncAttributeMaxDynamicSharedMemorySize, 98304);
        cudaFuncSetAttribute(sage_gemm_mma<256, false>,
                             cudaFuncAttributeMaxDynamicSharedMemorySize, 98304);
        attr_done = true;
    }

    const int gemm_blocks = (M + 127) / 128;

    // CSR build
    zero_deg<<<(N_NODES + 255) / 256, 256>>>();
    hist<<<(E + 255) / 256, 256>>>(ei, E);
    scan1<<<NB, SCAN_BLK>>>();
    scan2<<<1, 256>>>();
    scan3<<<(N_NODES + 255) / 256, 256>>>(E);
    fill<<<(E + 255) / 256, 256>>>(ei, E);

    // operand prep
    wconv<<<(128 * 128 + 128 * 256 + 255) / 256, 256>>>(Wl1, Wr1, Wl2, Wr2);
    convert_x<<<((long)M * 8 + 255) / 256, 256>>>(
        reinterpret_cast<const float4*>(x), xf);

    // layer 1
    gather_mean_f16<8><<<((long)M * 8 + 255) / 256, 256>>>(
        reinterpret_cast<const uint4*>(xf), m1);
    sage_gemm_mma<128, true><<<gemm_blocks, 256, 98304>>>(
        m1, xf, b1hi, b1lo, bl1, nullptr, hf, M);

    // layer 2
    gather_mean_f16<16><<<((long)M * 16 + 255) / 256, 256>>>(
        reinterpret_cast<const uint4*>(hf), m2);
    sage_gemm_mma<256, false><<<gemm_blocks, 256, 98304>>>(
        m2, hf, b2hi, b2lo, bl2, out, nullptr, M);
}